// round 3
// baseline (speedup 1.0000x reference)
#include <cuda_runtime.h>
#include <cuda_bf16.h>
#include <cstdint>

// ---------------------------------------------------------------------------
// FuseBlock: B=2, C=128, H=W=256.  Layout (b, c, h, w), HW = 65536.
// GEMMs on mma.sync m16n8k16 bf16 (3-term hi/lo compensation, fp32 accum).
// ---------------------------------------------------------------------------

#define EPSV   1e-6f

__device__ float g_bufA[100663296];   // 2*768*65536
__device__ float g_bufB[100663296];
__device__ float g_misc[2097152];

#define OFF_M1   0
#define OFF_R1   131072
#define OFF_M2   262144
#define OFF_R2   393216
#define OFF_M3   524288
#define OFF_R3   655360
#define OFF_S1   786432
#define OFF_T1   787200
#define OFF_S2   787968
#define OFF_T2   788224
#define OFF_DS   788480
#define OFF_DT   788992
#define OFF_WBF  789504     // bf16 region starts here (cast to __nv_bfloat16*)

// bf16-element offsets inside the WBF region
#define WO_W1HI  0
#define WO_W1LO  98304
#define WO_P1HI  196608
#define WO_P1LO  229376
#define WO_W2HI  262144
#define WO_W2LO  294912
#define WO_P2HI  327680
#define WO_P2LO  344064

#define OFF_X1   50331648
#define OFF_G    50331648

// ---------------------------------------------------------------------------
__device__ __forceinline__ void mma16816(float* d, const uint32_t* a, const uint32_t* b) {
    asm volatile(
        "mma.sync.aligned.m16n8k16.row.col.f32.bf16.bf16.f32 "
        "{%0,%1,%2,%3}, {%4,%5,%6,%7}, {%8,%9}, {%0,%1,%2,%3};"
        : "+f"(d[0]), "+f"(d[1]), "+f"(d[2]), "+f"(d[3])
        : "r"(a[0]), "r"(a[1]), "r"(a[2]), "r"(a[3]), "r"(b[0]), "r"(b[1]));
}

// ---------------------------------------------------------------------------
// mma GEMM: C[128 out-ch @ m0, 128 pix @ n0] = A[m,K] @ B[K, pix]
// MODE 1: out = colRstd[n]*(acc - colMean[n]*rowS[o]) + rowT[o]
// MODE 2: out = Xres[o,n] + acc*scaleRow[o]
// MODE 3: MODE2 epilogue; B element = v * LN2(attn) computed during staging
// smem: Bs_hi/Bs_lo [128 n][136 k] bf16 (dynamic, 69632 B)
// ---------------------------------------------------------------------------
template <int MODE>
__global__ __launch_bounds__(256)
void mma_gemm(const __nv_bfloat16* __restrict__ Ahi, const __nv_bfloat16* __restrict__ Alo,
              const float* __restrict__ B, float* __restrict__ Cc,
              int K, int CB, int CO,
              const float* __restrict__ colMean, const float* __restrict__ colRstd,
              const float* __restrict__ rowS, const float* __restrict__ rowT,
              const float* __restrict__ vbuf, const float* __restrict__ lnW,
              const float* __restrict__ lnB, const float* __restrict__ Xres,
              const float* __restrict__ scaleRow)
{
    extern __shared__ __align__(16) char smem[];
    __nv_bfloat16* Bs_hi = reinterpret_cast<__nv_bfloat16*>(smem);
    __nv_bfloat16* Bs_lo = Bs_hi + 128 * 136;

    const int tid = threadIdx.x;
    const int wid = tid >> 5;
    const int lane = tid & 31;
    const int n0 = blockIdx.x * 128;
    const int m0 = blockIdx.y * 128;
    const int bg = n0 >> 16;
    const int hw0 = n0 & 65535;
    const int warp_m = wid & 3;      // 4 m-stripes of 32
    const int warp_n = wid >> 2;     // 2 n-stripes of 64
    const int g  = lane >> 2;        // group id 0..7
    const int th = lane & 3;         // thread-in-group

    float acc[2][8][4];
#pragma unroll
    for (int mt = 0; mt < 2; mt++)
#pragma unroll
        for (int nt = 0; nt < 8; nt++)
#pragma unroll
            for (int r = 0; r < 4; r++) acc[mt][nt][r] = 0.f;

    const int nchunks = K >> 7;
    for (int ch = 0; ch < nchunks; ch++) {
        const int kc = ch << 7;
        if (ch) __syncthreads();

        // ---- stage B chunk: gmem [k][pix] -> smem [pix][k], bf16 hi/lo ----
        for (int idx = tid; idx < 4096; idx += 256) {
            int k = idx >> 5, pg = (idx & 31) * 4;
            float4 v;
            if (MODE == 3) {
                const float* ap = B    + (((size_t)(bg * 256 + kc + k))       << 16) + hw0 + pg;
                const float* vp = vbuf + (((size_t)(bg * 768 + 512 + kc + k)) << 16) + hw0 + pg;
                float4 a4 = *reinterpret_cast<const float4*>(ap);
                float4 v4 = *reinterpret_cast<const float4*>(vp);
                float4 m4 = *reinterpret_cast<const float4*>(colMean + n0 + pg);
                float4 r4 = *reinterpret_cast<const float4*>(colRstd + n0 + pg);
                float wc = lnW[kc + k], bc = lnB[kc + k];
                v.x = v4.x * ((a4.x - m4.x) * r4.x * wc + bc);
                v.y = v4.y * ((a4.y - m4.y) * r4.y * wc + bc);
                v.z = v4.z * ((a4.z - m4.z) * r4.z * wc + bc);
                v.w = v4.w * ((a4.w - m4.w) * r4.w * wc + bc);
            } else {
                v = *reinterpret_cast<const float4*>(
                        B + (((size_t)(bg * CB + kc + k)) << 16) + hw0 + pg);
            }
            float vv[4] = {v.x, v.y, v.z, v.w};
#pragma unroll
            for (int j = 0; j < 4; j++) {
                __nv_bfloat16 h = __float2bfloat16(vv[j]);
                __nv_bfloat16 l = __float2bfloat16(vv[j] - __bfloat162float(h));
                Bs_hi[(pg + j) * 136 + k] = h;
                Bs_lo[(pg + j) * 136 + k] = l;
            }
        }
        __syncthreads();

        // ---- 8 k-steps of 16 ----
#pragma unroll
        for (int ks = 0; ks < 8; ks++) {
            // A fragments straight from gmem (L1-resident weights)
            uint32_t ah[2][4], al[2][4];
#pragma unroll
            for (int mt = 0; mt < 2; mt++) {
                int r = m0 + warp_m * 32 + mt * 16 + g;
                size_t base = (size_t)r * K + kc + ks * 16 + th * 2;
                ah[mt][0] = *reinterpret_cast<const uint32_t*>(Ahi + base);
                ah[mt][1] = *reinterpret_cast<const uint32_t*>(Ahi + base + (size_t)8 * K);
                ah[mt][2] = *reinterpret_cast<const uint32_t*>(Ahi + base + 8);
                ah[mt][3] = *reinterpret_cast<const uint32_t*>(Ahi + base + (size_t)8 * K + 8);
                al[mt][0] = *reinterpret_cast<const uint32_t*>(Alo + base);
                al[mt][1] = *reinterpret_cast<const uint32_t*>(Alo + base + (size_t)8 * K);
                al[mt][2] = *reinterpret_cast<const uint32_t*>(Alo + base + 8);
                al[mt][3] = *reinterpret_cast<const uint32_t*>(Alo + base + (size_t)8 * K + 8);
            }
            // B fragments from smem
            uint32_t bh[8][2], bl[8][2];
#pragma unroll
            for (int nt = 0; nt < 8; nt++) {
                int n = warp_n * 64 + nt * 8 + g;
                int ko = ks * 16 + th * 2;
                bh[nt][0] = *reinterpret_cast<const uint32_t*>(&Bs_hi[n * 136 + ko]);
                bh[nt][1] = *reinterpret_cast<const uint32_t*>(&Bs_hi[n * 136 + ko + 8]);
                bl[nt][0] = *reinterpret_cast<const uint32_t*>(&Bs_lo[n * 136 + ko]);
                bl[nt][1] = *reinterpret_cast<const uint32_t*>(&Bs_lo[n * 136 + ko + 8]);
            }
#pragma unroll
            for (int mt = 0; mt < 2; mt++)
#pragma unroll
                for (int nt = 0; nt < 8; nt++) {
                    mma16816(acc[mt][nt], ah[mt], bh[nt]);
                    mma16816(acc[mt][nt], ah[mt], bl[nt]);
                    mma16816(acc[mt][nt], al[mt], bh[nt]);
                }
        }
    }

    // ---- epilogue ----
#pragma unroll
    for (int mt = 0; mt < 2; mt++) {
#pragma unroll
        for (int half = 0; half < 2; half++) {        // d0d1 row g, d2d3 row g+8
            int o = m0 + warp_m * 32 + mt * 16 + g + half * 8;
            if (MODE == 1) {
                float sv = rowS[o], tv = rowT[o];
#pragma unroll
                for (int nt = 0; nt < 8; nt++) {
                    int col = warp_n * 64 + nt * 8 + th * 2;
                    float2 cm = *reinterpret_cast<const float2*>(colMean + n0 + col);
                    float2 cr = *reinterpret_cast<const float2*>(colRstd + n0 + col);
                    float d0 = acc[mt][nt][half * 2 + 0];
                    float d1 = acc[mt][nt][half * 2 + 1];
                    float2 ov;
                    ov.x = cr.x * (d0 - cm.x * sv) + tv;
                    ov.y = cr.y * (d1 - cm.y * sv) + tv;
                    *reinterpret_cast<float2*>(
                        Cc + (((size_t)(bg * CO + o)) << 16) + hw0 + col) = ov;
                }
            } else {
                float sc = scaleRow[o];
#pragma unroll
                for (int nt = 0; nt < 8; nt++) {
                    int col = warp_n * 64 + nt * 8 + th * 2;
                    size_t ix = (((size_t)(bg * CO + o)) << 16) + hw0 + col;
                    float2 xr = *reinterpret_cast<const float2*>(Xres + ix);
                    float2 ov;
                    ov.x = xr.x + acc[mt][nt][half * 2 + 0] * sc;
                    ov.y = xr.y + acc[mt][nt][half * 2 + 1] * sc;
                    *reinterpret_cast<float2*>(Cc + ix) = ov;
                }
            }
        }
    }
}

// ---------------------------------------------------------------------------
// per-pixel channel mean / rstd
// ---------------------------------------------------------------------------
__global__ void stats_kernel(const float* __restrict__ in, float* __restrict__ mean,
                             float* __restrict__ rstd, int C) {
    int p = blockIdx.x * blockDim.x + threadIdx.x;
    int b = p >> 16, hw = p & 65535;
    const float* base = in + ((size_t)(b * C) << 16) + hw;
    float s = 0.f, ss = 0.f;
    for (int c = 0; c < C; c += 4) {
        float v0 = base[(size_t)(c + 0) << 16];
        float v1 = base[(size_t)(c + 1) << 16];
        float v2 = base[(size_t)(c + 2) << 16];
        float v3 = base[(size_t)(c + 3) << 16];
        s  += v0 + v1 + v2 + v3;
        ss += v0 * v0 + v1 * v1 + v2 * v2 + v3 * v3;
    }
    float invC = 1.f / (float)C;
    float m = s * invC;
    float var = ss * invC - m * m;
    mean[p] = m;
    rstd[p] = rsqrtf(var + EPSV);
}

// ---------------------------------------------------------------------------
// fold LN into conv weight + split hi/lo bf16.
//  nw==nullptr -> scale 1 ; nb==nullptr -> no LN-bias term
// ---------------------------------------------------------------------------
__global__ void fold_kernel(const float* __restrict__ wmat, const float* __restrict__ nw,
                            const float* __restrict__ nb, const float* __restrict__ bias,
                            __nv_bfloat16* __restrict__ whi, __nv_bfloat16* __restrict__ wlo,
                            float* __restrict__ srow, float* __restrict__ trow,
                            int M, int K) {
    int o = blockIdx.x * blockDim.x + threadIdx.x;
    if (o >= M) return;
    float s = 0.f, t = 0.f;
    for (int c = 0; c < K; c++) {
        float wv  = wmat[o * K + c];
        float wpv = nw ? wv * nw[c] : wv;
        __nv_bfloat16 h = __float2bfloat16(wpv);
        __nv_bfloat16 l = __float2bfloat16(wpv - __bfloat162float(h));
        whi[o * K + c] = h;
        wlo[o * K + c] = l;
        s += wpv;
        if (nb) t += wv * nb[c];
    }
    if (bias) t += bias[o];
    srow[o] = s;
    trow[o] = t;
}

// ---------------------------------------------------------------------------
__global__ void dwconv_kernel(const float* __restrict__ in, const float* __restrict__ w,
                              float* __restrict__ out, int C) {
    int z = blockIdx.z;
    int b = z / C, c = z - b * C;
    __shared__ float tile[10][34];
    int h0 = blockIdx.y * 8, w0 = blockIdx.x * 32;
    const float* base = in + ((size_t)(b * C + c) << 16);
    int tid = threadIdx.y * 32 + threadIdx.x;
    for (int idx = tid; idx < 340; idx += 256) {
        int r = idx / 34, cc = idx - r * 34;
        int gh = h0 - 1 + r, gw = w0 - 1 + cc;
        float v = 0.f;
        if (gh >= 0 && gh < 256 && gw >= 0 && gw < 256) v = base[gh * 256 + gw];
        tile[r][cc] = v;
    }
    __syncthreads();
    const float* wc = w + c * 9;
    int ty = threadIdx.y, tx = threadIdx.x;
    float s = wc[0] * tile[ty][tx]     + wc[1] * tile[ty][tx + 1]     + wc[2] * tile[ty][tx + 2]
            + wc[3] * tile[ty + 1][tx] + wc[4] * tile[ty + 1][tx + 1] + wc[5] * tile[ty + 1][tx + 2]
            + wc[6] * tile[ty + 2][tx] + wc[7] * tile[ty + 2][tx + 1] + wc[8] * tile[ty + 2][tx + 2];
    out[((size_t)(b * C + c) << 16) + (h0 + ty) * 256 + (w0 + tx)] = s;
}

// ---------------------------------------------------------------------------
__global__ void gate_kernel(const float* __restrict__ h, const float* __restrict__ wdw,
                            float* __restrict__ g) {
    int z = blockIdx.z;
    int b = z >> 7, c = z & 127;
    __shared__ float t1s[10][34];
    __shared__ float t2s[10][34];
    int h0 = blockIdx.y * 8, w0 = blockIdx.x * 32;
    const float* base1 = h + ((size_t)(b * 256 + c) << 16);
    const float* base2 = h + ((size_t)(b * 256 + c + 128) << 16);
    int tid = threadIdx.y * 32 + threadIdx.x;
    for (int idx = tid; idx < 340; idx += 256) {
        int r = idx / 34, cc = idx - r * 34;
        int gh = h0 - 1 + r, gw = w0 - 1 + cc;
        bool ok = (gh >= 0 && gh < 256 && gw >= 0 && gw < 256);
        t1s[r][cc] = ok ? base1[gh * 256 + gw] : 0.f;
        t2s[r][cc] = ok ? base2[gh * 256 + gw] : 0.f;
    }
    __syncthreads();
    const float* w1 = wdw + (size_t)c * 9;
    const float* w2 = wdw + (size_t)(c + 128) * 9;
    int ty = threadIdx.y, tx = threadIdx.x;
    float a1 = w1[0]*t1s[ty][tx]   + w1[1]*t1s[ty][tx+1]   + w1[2]*t1s[ty][tx+2]
             + w1[3]*t1s[ty+1][tx] + w1[4]*t1s[ty+1][tx+1] + w1[5]*t1s[ty+1][tx+2]
             + w1[6]*t1s[ty+2][tx] + w1[7]*t1s[ty+2][tx+1] + w1[8]*t1s[ty+2][tx+2];
    float a2 = w2[0]*t2s[ty][tx]   + w2[1]*t2s[ty][tx+1]   + w2[2]*t2s[ty][tx+2]
             + w2[3]*t2s[ty+1][tx] + w2[4]*t2s[ty+1][tx+1] + w2[5]*t2s[ty+1][tx+2]
             + w2[6]*t2s[ty+2][tx] + w2[7]*t2s[ty+2][tx+1] + w2[8]*t2s[ty+2][tx+2];
    g[((size_t)(b * 128 + c) << 16) + (h0 + ty) * 256 + (w0 + tx)] = a1 * a2;
}

// ---------------------------------------------------------------------------
__global__ __launch_bounds__(256)
void attn_kernel(const float* __restrict__ qkv, float* __restrict__ attn) {
    int z = blockIdx.z;
    int b = z >> 5;
    int cg = (z & 31) * 8;
    int ph = blockIdx.y, pwg = blockIdx.x;
    __shared__ float sq[8][4][72];
    __shared__ float sk[8][4][72];

    int t = threadIdx.x;
    {
        int i = t >> 5, col = t & 31;
        int lp = col >> 3, j = col & 7;
        int off = (ph * 8 + i) * 256 + pwg * 32 + col;
#pragma unroll
        for (int cidx = 0; cidx < 8; cidx++) {
            int c = cg + cidx;
            sq[cidx][lp][i * 8 + j] = qkv[((size_t)(b * 768 + c)       << 16) + off];
            sk[cidx][lp][i * 8 + j] = qkv[((size_t)(b * 768 + 256 + c) << 16) + off];
        }
    }
    __syncthreads();

    int cp   = t >> 3;
    int cidx = cp >> 2;
    int lp   = cp & 3;
    int i    = t & 7;

    float acc[8];
#pragma unroll
    for (int j = 0; j < 8; j++) acc[j] = 0.f;

#pragma unroll
    for (int a = 0; a < 8; a++) {
        int ra = (i - a) & 7;
        float qr[8], kr[8];
        *reinterpret_cast<float4*>(&qr[0]) = *reinterpret_cast<const float4*>(&sq[cidx][lp][a * 8]);
        *reinterpret_cast<float4*>(&qr[4]) = *reinterpret_cast<const float4*>(&sq[cidx][lp][a * 8 + 4]);
        *reinterpret_cast<float4*>(&kr[0]) = *reinterpret_cast<const float4*>(&sk[cidx][lp][ra * 8]);
        *reinterpret_cast<float4*>(&kr[4]) = *reinterpret_cast<const float4*>(&sk[cidx][lp][ra * 8 + 4]);
#pragma unroll
        for (int bq = 0; bq < 8; bq++)
#pragma unroll
            for (int j = 0; j < 8; j++)
                acc[j] += qr[bq] * kr[(j - bq) & 7];
    }

    size_t obase = (((size_t)(b * 256 + cg + cidx)) << 16)
                 + (ph * 8 + i) * 256 + pwg * 32 + lp * 8;
    float4 o0, o1;
    o0.x = acc[0]; o0.y = acc[1]; o0.z = acc[2]; o0.w = acc[3];
    o1.x = acc[4]; o1.y = acc[5]; o1.z = acc[6]; o1.w = acc[7];
    *reinterpret_cast<float4*>(attn + obase)     = o0;
    *reinterpret_cast<float4*>(attn + obase + 4) = o1;
}

// ---------------------------------------------------------------------------
#define GEMM_SMEM 69632

extern "C" void kernel_launch(void* const* d_in, const int* in_sizes, int n_in,
                              void* d_out, int out_size) {
    const float* x      = (const float*)d_in[0];
    const float* n1w    = (const float*)d_in[1];
    const float* n1b    = (const float*)d_in[2];
    const float* w_h1   = (const float*)d_in[3];
    const float* w_dw1  = (const float*)d_in[4];
    const float* n2w    = (const float*)d_in[5];
    const float* n2b    = (const float*)d_in[6];
    const float* w_p1   = (const float*)d_in[7];
    const float* n3w    = (const float*)d_in[8];
    const float* n3b    = (const float*)d_in[9];
    const float* w_h2   = (const float*)d_in[10];
    const float* b_h2   = (const float*)d_in[11];
    const float* w_dw2  = (const float*)d_in[12];
    const float* w_p2   = (const float*)d_in[13];
    const float* scale1 = (const float*)d_in[14];
    const float* scale2 = (const float*)d_in[15];
    float* out = (float*)d_out;

    float *bufA, *bufB, *misc;
    cudaGetSymbolAddress((void**)&bufA, g_bufA);
    cudaGetSymbolAddress((void**)&bufB, g_bufB);
    cudaGetSymbolAddress((void**)&misc, g_misc);

    float* m1 = misc + OFF_M1;
    float* r1 = misc + OFF_R1;
    float* m2 = misc + OFF_M2;
    float* r2 = misc + OFF_R2;
    float* m3 = misc + OFF_M3;
    float* r3 = misc + OFF_R3;
    float* s1 = misc + OFF_S1;
    float* t1 = misc + OFF_T1;
    float* s2 = misc + OFF_S2;
    float* t2 = misc + OFF_T2;
    float* ds = misc + OFF_DS;
    float* dt = misc + OFF_DT;
    __nv_bfloat16* wbf = reinterpret_cast<__nv_bfloat16*>(misc + OFF_WBF);
    __nv_bfloat16* W1hi = wbf + WO_W1HI;
    __nv_bfloat16* W1lo = wbf + WO_W1LO;
    __nv_bfloat16* P1hi = wbf + WO_P1HI;
    __nv_bfloat16* P1lo = wbf + WO_P1LO;
    __nv_bfloat16* W2hi = wbf + WO_W2HI;
    __nv_bfloat16* W2lo = wbf + WO_W2LO;
    __nv_bfloat16* P2hi = wbf + WO_P2HI;
    __nv_bfloat16* P2lo = wbf + WO_P2LO;

    cudaFuncSetAttribute(mma_gemm<1>, cudaFuncAttributeMaxDynamicSharedMemorySize, GEMM_SMEM);
    cudaFuncSetAttribute(mma_gemm<2>, cudaFuncAttributeMaxDynamicSharedMemorySize, GEMM_SMEM);
    cudaFuncSetAttribute(mma_gemm<3>, cudaFuncAttributeMaxDynamicSharedMemorySize, GEMM_SMEM);

    // stats + weight folds / bf16 splits
    stats_kernel<<<512, 256>>>(x, m1, r1, 128);
    fold_kernel<<<3, 256>>>(w_h1, n1w, n1b, nullptr, W1hi, W1lo, s1, t1, 768, 128);
    fold_kernel<<<1, 256>>>(w_h2, n3w, n3b, b_h2,   W2hi, W2lo, s2, t2, 256, 128);
    fold_kernel<<<1, 128>>>(w_p1, nullptr, nullptr, nullptr, P1hi, P1lo, ds, dt, 128, 256);
    fold_kernel<<<1, 128>>>(w_p2, nullptr, nullptr, nullptr, P2hi, P2lo, ds, dt, 128, 128);

    // K1: hidden = LN1-folded conv1x1 (128 -> 768)
    mma_gemm<1><<<dim3(1024, 6), 256, GEMM_SMEM>>>(W1hi, W1lo, x, bufA, 128, 128, 768,
                                                   m1, r1, s1, t1,
                                                   nullptr, nullptr, nullptr, nullptr, nullptr);
    // K2: depthwise 3x3 over 768 channels
    dwconv_kernel<<<dim3(8, 32, 1536), dim3(32, 8)>>>(bufA, w_dw1, bufB, 768);

    // K3a: patch circular conv (q = ch 0..255, k = ch 256..511 of qkv)
    attn_kernel<<<dim3(8, 32, 64), 256>>>(bufB, bufA);
    stats_kernel<<<512, 256>>>(bufA, m2, r2, 256);

    // K3b: x1 = x + scale1 * ( w_p1 @ ( v * LN2(attn) ) )
    mma_gemm<3><<<dim3(1024, 1), 256, GEMM_SMEM>>>(P1hi, P1lo, bufA, bufA + OFF_X1, 256, 256, 128,
                                                   m2, r2, nullptr, nullptr,
                                                   bufB, n2w, n2b, x, scale1);

    // FFN branch
    stats_kernel<<<512, 256>>>(bufA + OFF_X1, m3, r3, 128);
    mma_gemm<1><<<dim3(1024, 2), 256, GEMM_SMEM>>>(W2hi, W2lo, bufA + OFF_X1, bufB, 128, 128, 256,
                                                   m3, r3, s2, t2,
                                                   nullptr, nullptr, nullptr, nullptr, nullptr);
    gate_kernel<<<dim3(8, 32, 256), dim3(32, 8)>>>(bufB, w_dw2, bufB + OFF_G);
    mma_gemm<2><<<dim3(1024, 1), 256, GEMM_SMEM>>>(P2hi, P2lo, bufB + OFF_G, out, 128, 128, 128,
                                                   nullptr, nullptr, nullptr, nullptr,
                                                   nullptr, nullptr, nullptr,
                                                   bufA + OFF_X1, scale2);
}

// round 4
// speedup vs baseline: 1.5800x; 1.5800x over previous
#include <cuda_runtime.h>
#include <cuda_bf16.h>
#include <cstdint>

// ---------------------------------------------------------------------------
// FuseBlock: B=2, C=128, H=W=256.  Layout (b, c, h, w), HW = 65536.
// GEMMs on mma.sync m16n8k16 bf16 (3-term hi/lo compensation, fp32 accum).
// B smem layout: word[kpair][pixel] (k-even low half, k-odd high half)
// -> staging stores STS.128 conflict-free, frag loads LDS.32 conflict-free.
// ---------------------------------------------------------------------------

#define EPSV   1e-6f

__device__ float g_bufA[100663296];   // 2*768*65536
__device__ float g_bufB[100663296];
__device__ float g_misc[2097152];

#define OFF_M1   0
#define OFF_R1   131072
#define OFF_M2   262144
#define OFF_R2   393216
#define OFF_M3   524288
#define OFF_R3   655360
#define OFF_S1   786432
#define OFF_T1   787200
#define OFF_S2   787968
#define OFF_T2   788224
#define OFF_DS   788480
#define OFF_DT   788992
#define OFF_WBF  789504     // bf16 region starts here

#define WO_W1HI  0
#define WO_W1LO  98304
#define WO_P1HI  196608
#define WO_P1LO  229376
#define WO_W2HI  262144
#define WO_W2LO  294912
#define WO_P2HI  327680
#define WO_P2LO  344064

#define OFF_X1   50331648
#define OFF_G    50331648

// ---------------------------------------------------------------------------
__device__ __forceinline__ void mma16816(float* d, const uint32_t* a, const uint32_t* b) {
    asm volatile(
        "mma.sync.aligned.m16n8k16.row.col.f32.bf16.bf16.f32 "
        "{%0,%1,%2,%3}, {%4,%5,%6,%7}, {%8,%9}, {%0,%1,%2,%3};"
        : "+f"(d[0]), "+f"(d[1]), "+f"(d[2]), "+f"(d[3])
        : "r"(a[0]), "r"(a[1]), "r"(a[2]), "r"(a[3]), "r"(b[0]), "r"(b[1]));
}

__device__ __forceinline__ uint32_t pack_bf16x2(float lo_val, float hi_val) {
    __nv_bfloat16 l = __float2bfloat16(lo_val);
    __nv_bfloat16 h = __float2bfloat16(hi_val);
    return (uint32_t)__bfloat16_as_ushort(l) | ((uint32_t)__bfloat16_as_ushort(h) << 16);
}

// ---------------------------------------------------------------------------
// mma GEMM: C[128 out-ch @ m0, 128 pix @ n0] = A[m,K] @ B[K, pix]
// MODE 1: out = colRstd[n]*(acc - colMean[n]*rowS[o]) + rowT[o]
// MODE 2: out = Xres[o,n] + acc*scaleRow[o]
// MODE 3: MODE2 epilogue; B element = v * LN2(attn) computed during staging
// smem: BsHi/BsLo word[64 kpair][136 pix]  (69632 B dynamic)
// ---------------------------------------------------------------------------
#define BROW 136

template <int MODE>
__global__ __launch_bounds__(256)
void mma_gemm(const __nv_bfloat16* __restrict__ Ahi, const __nv_bfloat16* __restrict__ Alo,
              const float* __restrict__ B, float* __restrict__ Cc,
              int K, int CB, int CO,
              const float* __restrict__ colMean, const float* __restrict__ colRstd,
              const float* __restrict__ rowS, const float* __restrict__ rowT,
              const float* __restrict__ vbuf, const float* __restrict__ lnW,
              const float* __restrict__ lnB, const float* __restrict__ Xres,
              const float* __restrict__ scaleRow)
{
    extern __shared__ __align__(16) char smem[];
    uint32_t* BsHi = reinterpret_cast<uint32_t*>(smem);
    uint32_t* BsLo = BsHi + 64 * BROW;

    const int tid = threadIdx.x;
    const int wid = tid >> 5;
    const int lane = tid & 31;
    const int n0 = blockIdx.x * 128;
    const int m0 = blockIdx.y * 128;
    const int bg = n0 >> 16;
    const int hw0 = n0 & 65535;
    const int warp_m = wid & 3;      // 4 m-stripes of 32
    const int warp_n = wid >> 2;     // 2 n-stripes of 64
    const int g  = lane >> 2;        // group id 0..7
    const int th = lane & 3;         // thread-in-group

    float acc[2][8][4];
#pragma unroll
    for (int mt = 0; mt < 2; mt++)
#pragma unroll
        for (int nt = 0; nt < 8; nt++)
#pragma unroll
            for (int r = 0; r < 4; r++) acc[mt][nt][r] = 0.f;

    const int nchunks = K >> 7;
    for (int ch = 0; ch < nchunks; ch++) {
        const int kc = ch << 7;
        if (ch) __syncthreads();

        // ---- stage B chunk: rows k0=kc+2kp, k1=k0+1; pack (k0,k1) per pixel ----
        // warp-uniform kp; lanes cover 128 pixels in float4 groups
#pragma unroll
        for (int it = 0; it < 8; it++) {
            int idx = tid + it * 256;
            int kp = idx >> 5;                 // 0..63
            int pg = (idx & 31) * 4;           // pixel group
            int k0 = kc + kp * 2;
            float4 va, vb;
            if (MODE == 3) {
                float4 a0 = *reinterpret_cast<const float4*>(
                    B + (((size_t)(bg * 256 + k0))     << 16) + hw0 + pg);
                float4 a1 = *reinterpret_cast<const float4*>(
                    B + (((size_t)(bg * 256 + k0 + 1)) << 16) + hw0 + pg);
                float4 v0 = *reinterpret_cast<const float4*>(
                    vbuf + (((size_t)(bg * 768 + 512 + k0))     << 16) + hw0 + pg);
                float4 v1 = *reinterpret_cast<const float4*>(
                    vbuf + (((size_t)(bg * 768 + 512 + k0 + 1)) << 16) + hw0 + pg);
                float4 m4 = *reinterpret_cast<const float4*>(colMean + n0 + pg);
                float4 r4 = *reinterpret_cast<const float4*>(colRstd + n0 + pg);
                float wc0 = lnW[k0], bc0 = lnB[k0];
                float wc1 = lnW[k0 + 1], bc1 = lnB[k0 + 1];
                va.x = v0.x * ((a0.x - m4.x) * r4.x * wc0 + bc0);
                va.y = v0.y * ((a0.y - m4.y) * r4.y * wc0 + bc0);
                va.z = v0.z * ((a0.z - m4.z) * r4.z * wc0 + bc0);
                va.w = v0.w * ((a0.w - m4.w) * r4.w * wc0 + bc0);
                vb.x = v1.x * ((a1.x - m4.x) * r4.x * wc1 + bc1);
                vb.y = v1.y * ((a1.y - m4.y) * r4.y * wc1 + bc1);
                vb.z = v1.z * ((a1.z - m4.z) * r4.z * wc1 + bc1);
                vb.w = v1.w * ((a1.w - m4.w) * r4.w * wc1 + bc1);
            } else {
                va = *reinterpret_cast<const float4*>(
                    B + (((size_t)(bg * CB + k0))     << 16) + hw0 + pg);
                vb = *reinterpret_cast<const float4*>(
                    B + (((size_t)(bg * CB + k0 + 1)) << 16) + hw0 + pg);
            }
            float a[4] = {va.x, va.y, va.z, va.w};
            float b[4] = {vb.x, vb.y, vb.z, vb.w};
            uint4 H, L;
            uint32_t* hp = &H.x;
            uint32_t* lp = &L.x;
#pragma unroll
            for (int j = 0; j < 4; j++) {
                __nv_bfloat16 ha = __float2bfloat16(a[j]);
                __nv_bfloat16 hb = __float2bfloat16(b[j]);
                hp[j] = (uint32_t)__bfloat16_as_ushort(ha)
                      | ((uint32_t)__bfloat16_as_ushort(hb) << 16);
                lp[j] = pack_bf16x2(a[j] - __bfloat162float(ha),
                                    b[j] - __bfloat162float(hb));
            }
            *reinterpret_cast<uint4*>(BsHi + kp * BROW + pg) = H;
            *reinterpret_cast<uint4*>(BsLo + kp * BROW + pg) = L;
        }
        __syncthreads();

        // ---- 8 k-steps of 16 ----
#pragma unroll
        for (int ks = 0; ks < 8; ks++) {
            // A fragments from gmem (L1-resident weights)
            uint32_t ah[2][4], al[2][4];
#pragma unroll
            for (int mt = 0; mt < 2; mt++) {
                int r = m0 + warp_m * 32 + mt * 16 + g;
                size_t base = (size_t)r * K + kc + ks * 16 + th * 2;
                ah[mt][0] = *reinterpret_cast<const uint32_t*>(Ahi + base);
                ah[mt][1] = *reinterpret_cast<const uint32_t*>(Ahi + base + (size_t)8 * K);
                ah[mt][2] = *reinterpret_cast<const uint32_t*>(Ahi + base + 8);
                ah[mt][3] = *reinterpret_cast<const uint32_t*>(Ahi + base + (size_t)8 * K + 8);
                al[mt][0] = *reinterpret_cast<const uint32_t*>(Alo + base);
                al[mt][1] = *reinterpret_cast<const uint32_t*>(Alo + base + (size_t)8 * K);
                al[mt][2] = *reinterpret_cast<const uint32_t*>(Alo + base + 8);
                al[mt][3] = *reinterpret_cast<const uint32_t*>(Alo + base + (size_t)8 * K + 8);
            }
            const int kp0 = ks * 8 + th;       // b0: k = th*2 (+16*ks)
            const int kp1 = ks * 8 + 4 + th;   // b1: k = th*2+8
#pragma unroll
            for (int nt = 0; nt < 8; nt++) {
                int n = warp_n * 64 + nt * 8 + g;
                uint32_t bh[2], bl[2];
                bh[0] = BsHi[kp0 * BROW + n];
                bh[1] = BsHi[kp1 * BROW + n];
                bl[0] = BsLo[kp0 * BROW + n];
                bl[1] = BsLo[kp1 * BROW + n];
#pragma unroll
                for (int mt = 0; mt < 2; mt++) {
                    mma16816(acc[mt][nt], ah[mt], bh);
                    mma16816(acc[mt][nt], ah[mt], bl);
                    mma16816(acc[mt][nt], al[mt], bh);
                }
            }
        }
    }

    // ---- epilogue ----
#pragma unroll
    for (int mt = 0; mt < 2; mt++) {
#pragma unroll
        for (int half = 0; half < 2; half++) {
            int o = m0 + warp_m * 32 + mt * 16 + g + half * 8;
            if (MODE == 1) {
                float sv = rowS[o], tv = rowT[o];
#pragma unroll
                for (int nt = 0; nt < 8; nt++) {
                    int col = warp_n * 64 + nt * 8 + th * 2;
                    float2 cm = *reinterpret_cast<const float2*>(colMean + n0 + col);
                    float2 cr = *reinterpret_cast<const float2*>(colRstd + n0 + col);
                    float d0 = acc[mt][nt][half * 2 + 0];
                    float d1 = acc[mt][nt][half * 2 + 1];
                    float2 ov;
                    ov.x = cr.x * (d0 - cm.x * sv) + tv;
                    ov.y = cr.y * (d1 - cm.y * sv) + tv;
                    *reinterpret_cast<float2*>(
                        Cc + (((size_t)(bg * CO + o)) << 16) + hw0 + col) = ov;
                }
            } else {
                float sc = scaleRow[o];
#pragma unroll
                for (int nt = 0; nt < 8; nt++) {
                    int col = warp_n * 64 + nt * 8 + th * 2;
                    size_t ix = (((size_t)(bg * CO + o)) << 16) + hw0 + col;
                    float2 xr = *reinterpret_cast<const float2*>(Xres + ix);
                    float2 ov;
                    ov.x = xr.x + acc[mt][nt][half * 2 + 0] * sc;
                    ov.y = xr.y + acc[mt][nt][half * 2 + 1] * sc;
                    *reinterpret_cast<float2*>(Cc + ix) = ov;
                }
            }
        }
    }
}

// ---------------------------------------------------------------------------
// per-pixel channel mean / rstd
// ---------------------------------------------------------------------------
__global__ void stats_kernel(const float* __restrict__ in, float* __restrict__ mean,
                             float* __restrict__ rstd, int C) {
    int p = blockIdx.x * blockDim.x + threadIdx.x;
    int b = p >> 16, hw = p & 65535;
    const float* base = in + ((size_t)(b * C) << 16) + hw;
    float s = 0.f, ss = 0.f;
    for (int c = 0; c < C; c += 4) {
        float v0 = base[(size_t)(c + 0) << 16];
        float v1 = base[(size_t)(c + 1) << 16];
        float v2 = base[(size_t)(c + 2) << 16];
        float v3 = base[(size_t)(c + 3) << 16];
        s  += v0 + v1 + v2 + v3;
        ss += v0 * v0 + v1 * v1 + v2 * v2 + v3 * v3;
    }
    float invC = 1.f / (float)C;
    float m = s * invC;
    float var = ss * invC - m * m;
    mean[p] = m;
    rstd[p] = rsqrtf(var + EPSV);
}

// ---------------------------------------------------------------------------
// fold LN into conv weight + split hi/lo bf16.  One WARP per output row.
// ---------------------------------------------------------------------------
__global__ void fold_kernel(const float* __restrict__ wmat, const float* __restrict__ nw,
                            const float* __restrict__ nb, const float* __restrict__ bias,
                            __nv_bfloat16* __restrict__ whi, __nv_bfloat16* __restrict__ wlo,
                            float* __restrict__ srow, float* __restrict__ trow,
                            int M, int K) {
    int o = blockIdx.x * (blockDim.x >> 5) + (threadIdx.x >> 5);
    int lane = threadIdx.x & 31;
    if (o >= M) return;
    float s = 0.f, t = 0.f;
    for (int c = lane; c < K; c += 32) {
        float wv  = wmat[o * K + c];
        float wpv = nw ? wv * nw[c] : wv;
        __nv_bfloat16 h = __float2bfloat16(wpv);
        __nv_bfloat16 l = __float2bfloat16(wpv - __bfloat162float(h));
        whi[o * K + c] = h;
        wlo[o * K + c] = l;
        s += wpv;
        if (nb) t += wv * nb[c];
    }
#pragma unroll
    for (int off = 16; off; off >>= 1) {
        s += __shfl_xor_sync(0xFFFFFFFFu, s, off);
        t += __shfl_xor_sync(0xFFFFFFFFu, t, off);
    }
    if (lane == 0) {
        srow[o] = s;
        trow[o] = t + (bias ? bias[o] : 0.f);
    }
}

// ---------------------------------------------------------------------------
__global__ void dwconv_kernel(const float* __restrict__ in, const float* __restrict__ w,
                              float* __restrict__ out, int C) {
    int z = blockIdx.z;
    int b = z / C, c = z - b * C;
    __shared__ float tile[10][34];
    int h0 = blockIdx.y * 8, w0 = blockIdx.x * 32;
    const float* base = in + ((size_t)(b * C + c) << 16);
    int tid = threadIdx.y * 32 + threadIdx.x;
    for (int idx = tid; idx < 340; idx += 256) {
        int r = idx / 34, cc = idx - r * 34;
        int gh = h0 - 1 + r, gw = w0 - 1 + cc;
        float v = 0.f;
        if (gh >= 0 && gh < 256 && gw >= 0 && gw < 256) v = base[gh * 256 + gw];
        tile[r][cc] = v;
    }
    __syncthreads();
    const float* wc = w + c * 9;
    int ty = threadIdx.y, tx = threadIdx.x;
    float s = wc[0] * tile[ty][tx]     + wc[1] * tile[ty][tx + 1]     + wc[2] * tile[ty][tx + 2]
            + wc[3] * tile[ty + 1][tx] + wc[4] * tile[ty + 1][tx + 1] + wc[5] * tile[ty + 1][tx + 2]
            + wc[6] * tile[ty + 2][tx] + wc[7] * tile[ty + 2][tx + 1] + wc[8] * tile[ty + 2][tx + 2];
    out[((size_t)(b * C + c) << 16) + (h0 + ty) * 256 + (w0 + tx)] = s;
}

// ---------------------------------------------------------------------------
__global__ void gate_kernel(const float* __restrict__ h, const float* __restrict__ wdw,
                            float* __restrict__ g) {
    int z = blockIdx.z;
    int b = z >> 7, c = z & 127;
    __shared__ float t1s[10][34];
    __shared__ float t2s[10][34];
    int h0 = blockIdx.y * 8, w0 = blockIdx.x * 32;
    const float* base1 = h + ((size_t)(b * 256 + c) << 16);
    const float* base2 = h + ((size_t)(b * 256 + c + 128) << 16);
    int tid = threadIdx.y * 32 + threadIdx.x;
    for (int idx = tid; idx < 340; idx += 256) {
        int r = idx / 34, cc = idx - r * 34;
        int gh = h0 - 1 + r, gw = w0 - 1 + cc;
        bool ok = (gh >= 0 && gh < 256 && gw >= 0 && gw < 256);
        t1s[r][cc] = ok ? base1[gh * 256 + gw] : 0.f;
        t2s[r][cc] = ok ? base2[gh * 256 + gw] : 0.f;
    }
    __syncthreads();
    const float* w1 = wdw + (size_t)c * 9;
    const float* w2 = wdw + (size_t)(c + 128) * 9;
    int ty = threadIdx.y, tx = threadIdx.x;
    float a1 = w1[0]*t1s[ty][tx]   + w1[1]*t1s[ty][tx+1]   + w1[2]*t1s[ty][tx+2]
             + w1[3]*t1s[ty+1][tx] + w1[4]*t1s[ty+1][tx+1] + w1[5]*t1s[ty+1][tx+2]
             + w1[6]*t1s[ty+2][tx] + w1[7]*t1s[ty+2][tx+1] + w1[8]*t1s[ty+2][tx+2];
    float a2 = w2[0]*t2s[ty][tx]   + w2[1]*t2s[ty][tx+1]   + w2[2]*t2s[ty][tx+2]
             + w2[3]*t2s[ty+1][tx] + w2[4]*t2s[ty+1][tx+1] + w2[5]*t2s[ty+1][tx+2]
             + w2[6]*t2s[ty+2][tx] + w2[7]*t2s[ty+2][tx+1] + w2[8]*t2s[ty+2][tx+2];
    g[((size_t)(b * 128 + c) << 16) + (h0 + ty) * 256 + (w0 + tx)] = a1 * a2;
}

// ---------------------------------------------------------------------------
__global__ __launch_bounds__(256)
void attn_kernel(const float* __restrict__ qkv, float* __restrict__ attn) {
    int z = blockIdx.z;
    int b = z >> 5;
    int cg = (z & 31) * 8;
    int ph = blockIdx.y, pwg = blockIdx.x;
    __shared__ float sq[8][4][72];
    __shared__ float sk[8][4][72];

    int t = threadIdx.x;
    {
        int i = t >> 5, col = t & 31;
        int lp = col >> 3, j = col & 7;
        int off = (ph * 8 + i) * 256 + pwg * 32 + col;
#pragma unroll
        for (int cidx = 0; cidx < 8; cidx++) {
            int c = cg + cidx;
            sq[cidx][lp][i * 8 + j] = qkv[((size_t)(b * 768 + c)       << 16) + off];
            sk[cidx][lp][i * 8 + j] = qkv[((size_t)(b * 768 + 256 + c) << 16) + off];
        }
    }
    __syncthreads();

    int cp   = t >> 3;
    int cidx = cp >> 2;
    int lp   = cp & 3;
    int i    = t & 7;

    float acc[8];
#pragma unroll
    for (int j = 0; j < 8; j++) acc[j] = 0.f;

#pragma unroll
    for (int a = 0; a < 8; a++) {
        int ra = (i - a) & 7;
        float qr[8], kr[8];
        *reinterpret_cast<float4*>(&qr[0]) = *reinterpret_cast<const float4*>(&sq[cidx][lp][a * 8]);
        *reinterpret_cast<float4*>(&qr[4]) = *reinterpret_cast<const float4*>(&sq[cidx][lp][a * 8 + 4]);
        *reinterpret_cast<float4*>(&kr[0]) = *reinterpret_cast<const float4*>(&sk[cidx][lp][ra * 8]);
        *reinterpret_cast<float4*>(&kr[4]) = *reinterpret_cast<const float4*>(&sk[cidx][lp][ra * 8 + 4]);
#pragma unroll
        for (int bq = 0; bq < 8; bq++)
#pragma unroll
            for (int j = 0; j < 8; j++)
                acc[j] += qr[bq] * kr[(j - bq) & 7];
    }

    size_t obase = (((size_t)(b * 256 + cg + cidx)) << 16)
                 + (ph * 8 + i) * 256 + pwg * 32 + lp * 8;
    float4 o0, o1;
    o0.x = acc[0]; o0.y = acc[1]; o0.z = acc[2]; o0.w = acc[3];
    o1.x = acc[4]; o1.y = acc[5]; o1.z = acc[6]; o1.w = acc[7];
    *reinterpret_cast<float4*>(attn + obase)     = o0;
    *reinterpret_cast<float4*>(attn + obase + 4) = o1;
}

// ---------------------------------------------------------------------------
#define GEMM_SMEM 69632

extern "C" void kernel_launch(void* const* d_in, const int* in_sizes, int n_in,
                              void* d_out, int out_size) {
    const float* x      = (const float*)d_in[0];
    const float* n1w    = (const float*)d_in[1];
    const float* n1b    = (const float*)d_in[2];
    const float* w_h1   = (const float*)d_in[3];
    const float* w_dw1  = (const float*)d_in[4];
    const float* n2w    = (const float*)d_in[5];
    const float* n2b    = (const float*)d_in[6];
    const float* w_p1   = (const float*)d_in[7];
    const float* n3w    = (const float*)d_in[8];
    const float* n3b    = (const float*)d_in[9];
    const float* w_h2   = (const float*)d_in[10];
    const float* b_h2   = (const float*)d_in[11];
    const float* w_dw2  = (const float*)d_in[12];
    const float* w_p2   = (const float*)d_in[13];
    const float* scale1 = (const float*)d_in[14];
    const float* scale2 = (const float*)d_in[15];
    float* out = (float*)d_out;

    float *bufA, *bufB, *misc;
    cudaGetSymbolAddress((void**)&bufA, g_bufA);
    cudaGetSymbolAddress((void**)&bufB, g_bufB);
    cudaGetSymbolAddress((void**)&misc, g_misc);

    float* m1 = misc + OFF_M1;
    float* r1 = misc + OFF_R1;
    float* m2 = misc + OFF_M2;
    float* r2 = misc + OFF_R2;
    float* m3 = misc + OFF_M3;
    float* r3 = misc + OFF_R3;
    float* s1 = misc + OFF_S1;
    float* t1 = misc + OFF_T1;
    float* s2 = misc + OFF_S2;
    float* t2 = misc + OFF_T2;
    float* ds = misc + OFF_DS;
    float* dt = misc + OFF_DT;
    __nv_bfloat16* wbf = reinterpret_cast<__nv_bfloat16*>(misc + OFF_WBF);
    __nv_bfloat16* W1hi = wbf + WO_W1HI;
    __nv_bfloat16* W1lo = wbf + WO_W1LO;
    __nv_bfloat16* P1hi = wbf + WO_P1HI;
    __nv_bfloat16* P1lo = wbf + WO_P1LO;
    __nv_bfloat16* W2hi = wbf + WO_W2HI;
    __nv_bfloat16* W2lo = wbf + WO_W2LO;
    __nv_bfloat16* P2hi = wbf + WO_P2HI;
    __nv_bfloat16* P2lo = wbf + WO_P2LO;

    cudaFuncSetAttribute(mma_gemm<1>, cudaFuncAttributeMaxDynamicSharedMemorySize, GEMM_SMEM);
    cudaFuncSetAttribute(mma_gemm<2>, cudaFuncAttributeMaxDynamicSharedMemorySize, GEMM_SMEM);
    cudaFuncSetAttribute(mma_gemm<3>, cudaFuncAttributeMaxDynamicSharedMemorySize, GEMM_SMEM);

    // stats + weight folds / bf16 splits (warp per row)
    stats_kernel<<<512, 256>>>(x, m1, r1, 128);
    fold_kernel<<<96, 256>>>(w_h1, n1w, n1b, nullptr, W1hi, W1lo, s1, t1, 768, 128);
    fold_kernel<<<32, 256>>>(w_h2, n3w, n3b, b_h2,   W2hi, W2lo, s2, t2, 256, 128);
    fold_kernel<<<16, 256>>>(w_p1, nullptr, nullptr, nullptr, P1hi, P1lo, ds, dt, 128, 256);
    fold_kernel<<<16, 256>>>(w_p2, nullptr, nullptr, nullptr, P2hi, P2lo, ds, dt, 128, 128);

    // K1: hidden = LN1-folded conv1x1 (128 -> 768)
    mma_gemm<1><<<dim3(1024, 6), 256, GEMM_SMEM>>>(W1hi, W1lo, x, bufA, 128, 128, 768,
                                                   m1, r1, s1, t1,
                                                   nullptr, nullptr, nullptr, nullptr, nullptr);
    // K2: depthwise 3x3 over 768 channels
    dwconv_kernel<<<dim3(8, 32, 1536), dim3(32, 8)>>>(bufA, w_dw1, bufB, 768);

    // K3a: patch circular conv (q = ch 0..255, k = ch 256..511 of qkv)
    attn_kernel<<<dim3(8, 32, 64), 256>>>(bufB, bufA);
    stats_kernel<<<512, 256>>>(bufA, m2, r2, 256);

    // K3b: x1 = x + scale1 * ( w_p1 @ ( v * LN2(attn) ) )
    mma_gemm<3><<<dim3(1024, 1), 256, GEMM_SMEM>>>(P1hi, P1lo, bufA, bufA + OFF_X1, 256, 256, 128,
                                                   m2, r2, nullptr, nullptr,
                                                   bufB, n2w, n2b, x, scale1);

    // FFN branch
    stats_kernel<<<512, 256>>>(bufA + OFF_X1, m3, r3, 128);
    mma_gemm<1><<<dim3(1024, 2), 256, GEMM_SMEM>>>(W2hi, W2lo, bufA + OFF_X1, bufB, 128, 128, 256,
                                                   m3, r3, s2, t2,
                                                   nullptr, nullptr, nullptr, nullptr, nullptr);
    gate_kernel<<<dim3(8, 32, 256), dim3(32, 8)>>>(bufB, w_dw2, bufB + OFF_G);
    mma_gemm<2><<<dim3(1024, 1), 256, GEMM_SMEM>>>(P2hi, P2lo, bufB + OFF_G, out, 128, 128, 128,
                                                   nullptr, nullptr, nullptr, nullptr,
                                                   nullptr, nullptr, nullptr,
                                                   bufA + OFF_X1, scale2);
}

// round 8
// speedup vs baseline: 2.2837x; 1.4454x over previous
#include <cuda_runtime.h>
#include <cuda_bf16.h>
#include <cstdint>

// ---------------------------------------------------------------------------
// FuseBlock: B=2, C=128, H=W=256.  Layout (b, c, h, w), HW = 65536.
// GEMMs on mma.sync m16n8k16 bf16 (3-term hi/lo compensation, fp32 accum).
// B smem word[kpair][pixel]; GEMM loops m-blocks against resident B tile.
// dwconv/gate: full-width 256x8 strips, 8 outputs/thread.
// ---------------------------------------------------------------------------

#define EPSV   1e-6f

__device__ float g_bufA[100663296];   // 2*768*65536
__device__ float g_bufB[100663296];
__device__ float g_misc[2097152];

#define OFF_M1   0
#define OFF_R1   131072
#define OFF_M2   262144
#define OFF_R2   393216
#define OFF_M3   524288
#define OFF_R3   655360
#define OFF_S1   786432
#define OFF_T1   787200
#define OFF_S2   787968
#define OFF_T2   788224
#define OFF_DS   788480
#define OFF_DT   788992
#define OFF_WBF  789504

#define WO_W1HI  0
#define WO_W1LO  98304
#define WO_P1HI  196608
#define WO_P1LO  229376
#define WO_W2HI  262144
#define WO_W2LO  294912
#define WO_P2HI  327680
#define WO_P2LO  344064

#define OFF_X1   50331648
#define OFF_G    50331648

// ---------------------------------------------------------------------------
__device__ __forceinline__ void mma16816(float* d, const uint32_t* a, const uint32_t* b) {
    asm volatile(
        "mma.sync.aligned.m16n8k16.row.col.f32.bf16.bf16.f32 "
        "{%0,%1,%2,%3}, {%4,%5,%6,%7}, {%8,%9}, {%0,%1,%2,%3};"
        : "+f"(d[0]), "+f"(d[1]), "+f"(d[2]), "+f"(d[3])
        : "r"(a[0]), "r"(a[1]), "r"(a[2]), "r"(a[3]), "r"(b[0]), "r"(b[1]));
}

__device__ __forceinline__ uint32_t pack_bf16x2(float lo_val, float hi_val) {
    __nv_bfloat16 l = __float2bfloat16(lo_val);
    __nv_bfloat16 h = __float2bfloat16(hi_val);
    return (uint32_t)__bfloat16_as_ushort(l) | ((uint32_t)__bfloat16_as_ushort(h) << 16);
}

// ---------------------------------------------------------------------------
// mma GEMM: C[mblocks*128 out-ch, 128 pix @ n0] = A[m,K] @ B[K, pix]
// B tile staged ONCE (when K==128), then mblocks m-stripes computed in-kernel.
// MODE 1: out = colRstd[n]*(acc - colMean[n]*rowS[o]) + rowT[o]
// MODE 2: out = Xres[o,n] + acc*scaleRow[o]
// MODE 3: MODE2 epilogue; B element = v * LN2(attn) computed during staging
// ---------------------------------------------------------------------------
#define BROW 136

template <int MODE>
__global__ __launch_bounds__(256)
void mma_gemm(const __nv_bfloat16* __restrict__ Ahi, const __nv_bfloat16* __restrict__ Alo,
              const float* __restrict__ B, float* __restrict__ Cc,
              int K, int CB, int CO, int mblocks,
              const float* __restrict__ colMean, const float* __restrict__ colRstd,
              const float* __restrict__ rowS, const float* __restrict__ rowT,
              const float* __restrict__ vbuf, const float* __restrict__ lnW,
              const float* __restrict__ lnB, const float* __restrict__ Xres,
              const float* __restrict__ scaleRow)
{
    extern __shared__ __align__(16) char smem[];
    uint32_t* BsHi = reinterpret_cast<uint32_t*>(smem);
    uint32_t* BsLo = BsHi + 64 * BROW;

    const int tid = threadIdx.x;
    const int wid = tid >> 5;
    const int lane = tid & 31;
    const int n0 = blockIdx.x * 128;
    const int bg = n0 >> 16;
    const int hw0 = n0 & 65535;
    const int warp_m = wid & 3;
    const int warp_n = wid >> 2;
    const int g  = lane >> 2;
    const int th = lane & 3;

    const int nchunks = K >> 7;

    for (int mb = 0; mb < mblocks; mb++) {
        const int m0 = mb * 128;

        float acc[2][8][4];
#pragma unroll
        for (int mt = 0; mt < 2; mt++)
#pragma unroll
            for (int nt = 0; nt < 8; nt++)
#pragma unroll
                for (int r = 0; r < 4; r++) acc[mt][nt][r] = 0.f;

        for (int ch = 0; ch < nchunks; ch++) {
            const int kc = ch << 7;

            if (mb == 0) {
                if (ch) __syncthreads();
                // ---- stage B chunk: pack rows (k0, k0+1) per pixel ----
#pragma unroll
                for (int it = 0; it < 8; it++) {
                    int idx = tid + it * 256;
                    int kp = idx >> 5;
                    int pg = (idx & 31) * 4;
                    int k0 = kc + kp * 2;
                    float4 va, vb;
                    if (MODE == 3) {
                        float4 a0 = *reinterpret_cast<const float4*>(
                            B + (((size_t)(bg * 256 + k0))     << 16) + hw0 + pg);
                        float4 a1 = *reinterpret_cast<const float4*>(
                            B + (((size_t)(bg * 256 + k0 + 1)) << 16) + hw0 + pg);
                        float4 v0 = *reinterpret_cast<const float4*>(
                            vbuf + (((size_t)(bg * 768 + 512 + k0))     << 16) + hw0 + pg);
                        float4 v1 = *reinterpret_cast<const float4*>(
                            vbuf + (((size_t)(bg * 768 + 512 + k0 + 1)) << 16) + hw0 + pg);
                        float4 m4 = *reinterpret_cast<const float4*>(colMean + n0 + pg);
                        float4 r4 = *reinterpret_cast<const float4*>(colRstd + n0 + pg);
                        float wc0 = lnW[k0], bc0 = lnB[k0];
                        float wc1 = lnW[k0 + 1], bc1 = lnB[k0 + 1];
                        va.x = v0.x * ((a0.x - m4.x) * r4.x * wc0 + bc0);
                        va.y = v0.y * ((a0.y - m4.y) * r4.y * wc0 + bc0);
                        va.z = v0.z * ((a0.z - m4.z) * r4.z * wc0 + bc0);
                        va.w = v0.w * ((a0.w - m4.w) * r4.w * wc0 + bc0);
                        vb.x = v1.x * ((a1.x - m4.x) * r4.x * wc1 + bc1);
                        vb.y = v1.y * ((a1.y - m4.y) * r4.y * wc1 + bc1);
                        vb.z = v1.z * ((a1.z - m4.z) * r4.z * wc1 + bc1);
                        vb.w = v1.w * ((a1.w - m4.w) * r4.w * wc1 + bc1);
                    } else {
                        va = *reinterpret_cast<const float4*>(
                            B + (((size_t)(bg * CB + k0))     << 16) + hw0 + pg);
                        vb = *reinterpret_cast<const float4*>(
                            B + (((size_t)(bg * CB + k0 + 1)) << 16) + hw0 + pg);
                    }
                    float a[4] = {va.x, va.y, va.z, va.w};
                    float b[4] = {vb.x, vb.y, vb.z, vb.w};
                    uint4 H, L;
                    uint32_t* hp = &H.x;
                    uint32_t* lp = &L.x;
#pragma unroll
                    for (int j = 0; j < 4; j++) {
                        __nv_bfloat16 ha = __float2bfloat16(a[j]);
                        __nv_bfloat16 hb = __float2bfloat16(b[j]);
                        hp[j] = (uint32_t)__bfloat16_as_ushort(ha)
                              | ((uint32_t)__bfloat16_as_ushort(hb) << 16);
                        lp[j] = pack_bf16x2(a[j] - __bfloat162float(ha),
                                            b[j] - __bfloat162float(hb));
                    }
                    *reinterpret_cast<uint4*>(BsHi + kp * BROW + pg) = H;
                    *reinterpret_cast<uint4*>(BsLo + kp * BROW + pg) = L;
                }
                __syncthreads();
            }

            // ---- 8 k-steps of 16 ----
#pragma unroll
            for (int ks = 0; ks < 8; ks++) {
                uint32_t ah[2][4], al[2][4];
#pragma unroll
                for (int mt = 0; mt < 2; mt++) {
                    int r = m0 + warp_m * 32 + mt * 16 + g;
                    size_t base = (size_t)r * K + kc + ks * 16 + th * 2;
                    ah[mt][0] = *reinterpret_cast<const uint32_t*>(Ahi + base);
                    ah[mt][1] = *reinterpret_cast<const uint32_t*>(Ahi + base + (size_t)8 * K);
                    ah[mt][2] = *reinterpret_cast<const uint32_t*>(Ahi + base + 8);
                    ah[mt][3] = *reinterpret_cast<const uint32_t*>(Ahi + base + (size_t)8 * K + 8);
                    al[mt][0] = *reinterpret_cast<const uint32_t*>(Alo + base);
                    al[mt][1] = *reinterpret_cast<const uint32_t*>(Alo + base + (size_t)8 * K);
                    al[mt][2] = *reinterpret_cast<const uint32_t*>(Alo + base + 8);
                    al[mt][3] = *reinterpret_cast<const uint32_t*>(Alo + base + (size_t)8 * K + 8);
                }
                const int kp0 = ks * 8 + th;
                const int kp1 = ks * 8 + 4 + th;
#pragma unroll
                for (int nt = 0; nt < 8; nt++) {
                    int n = warp_n * 64 + nt * 8 + g;
                    uint32_t bh[2], bl[2];
                    bh[0] = BsHi[kp0 * BROW + n];
                    bh[1] = BsHi[kp1 * BROW + n];
                    bl[0] = BsLo[kp0 * BROW + n];
                    bl[1] = BsLo[kp1 * BROW + n];
#pragma unroll
                    for (int mt = 0; mt < 2; mt++) {
                        mma16816(acc[mt][nt], ah[mt], bh);
                        mma16816(acc[mt][nt], ah[mt], bl);
                        mma16816(acc[mt][nt], al[mt], bh);
                    }
                }
            }
        }

        // ---- epilogue for this m-block ----
#pragma unroll
        for (int mt = 0; mt < 2; mt++) {
#pragma unroll
            for (int half = 0; half < 2; half++) {
                int o = m0 + warp_m * 32 + mt * 16 + g + half * 8;
                if (MODE == 1) {
                    float sv = rowS[o], tv = rowT[o];
#pragma unroll
                    for (int nt = 0; nt < 8; nt++) {
                        int col = warp_n * 64 + nt * 8 + th * 2;
                        float2 cm = *reinterpret_cast<const float2*>(colMean + n0 + col);
                        float2 cr = *reinterpret_cast<const float2*>(colRstd + n0 + col);
                        float d0 = acc[mt][nt][half * 2 + 0];
                        float d1 = acc[mt][nt][half * 2 + 1];
                        float2 ov;
                        ov.x = cr.x * (d0 - cm.x * sv) + tv;
                        ov.y = cr.y * (d1 - cm.y * sv) + tv;
                        *reinterpret_cast<float2*>(
                            Cc + (((size_t)(bg * CO + o)) << 16) + hw0 + col) = ov;
                    }
                } else {
                    float sc = scaleRow[o];
#pragma unroll
                    for (int nt = 0; nt < 8; nt++) {
                        int col = warp_n * 64 + nt * 8 + th * 2;
                        size_t ix = (((size_t)(bg * CO + o)) << 16) + hw0 + col;
                        float2 xr = *reinterpret_cast<const float2*>(Xres + ix);
                        float2 ov;
                        ov.x = xr.x + acc[mt][nt][half * 2 + 0] * sc;
                        ov.y = xr.y + acc[mt][nt][half * 2 + 1] * sc;
                        *reinterpret_cast<float2*>(Cc + ix) = ov;
                    }
                }
            }
        }
    }
}

// ---------------------------------------------------------------------------
__global__ void stats_kernel(const float* __restrict__ in, float* __restrict__ mean,
                             float* __restrict__ rstd, int C) {
    int p = blockIdx.x * blockDim.x + threadIdx.x;
    int b = p >> 16, hw = p & 65535;
    const float* base = in + ((size_t)(b * C) << 16) + hw;
    float s = 0.f, ss = 0.f;
    for (int c = 0; c < C; c += 4) {
        float v0 = base[(size_t)(c + 0) << 16];
        float v1 = base[(size_t)(c + 1) << 16];
        float v2 = base[(size_t)(c + 2) << 16];
        float v3 = base[(size_t)(c + 3) << 16];
        s  += v0 + v1 + v2 + v3;
        ss += v0 * v0 + v1 * v1 + v2 * v2 + v3 * v3;
    }
    float invC = 1.f / (float)C;
    float m = s * invC;
    float var = ss * invC - m * m;
    mean[p] = m;
    rstd[p] = rsqrtf(var + EPSV);
}

// ---------------------------------------------------------------------------
__global__ void fold_kernel(const float* __restrict__ wmat, const float* __restrict__ nw,
                            const float* __restrict__ nb, const float* __restrict__ bias,
                            __nv_bfloat16* __restrict__ whi, __nv_bfloat16* __restrict__ wlo,
                            float* __restrict__ srow, float* __restrict__ trow,
                            int M, int K) {
    int o = blockIdx.x * (blockDim.x >> 5) + (threadIdx.x >> 5);
    int lane = threadIdx.x & 31;
    if (o >= M) return;
    float s = 0.f, t = 0.f;
    for (int c = lane; c < K; c += 32) {
        float wv  = wmat[o * K + c];
        float wpv = nw ? wv * nw[c] : wv;
        __nv_bfloat16 h = __float2bfloat16(wpv);
        __nv_bfloat16 l = __float2bfloat16(wpv - __bfloat162float(h));
        whi[o * K + c] = h;
        wlo[o * K + c] = l;
        s += wpv;
        if (nb) t += wv * nb[c];
    }
#pragma unroll
    for (int off = 16; off; off >>= 1) {
        s += __shfl_xor_sync(0xFFFFFFFFu, s, off);
        t += __shfl_xor_sync(0xFFFFFFFFu, t, off);
    }
    if (lane == 0) {
        srow[o] = s;
        trow[o] = t + (bias ? bias[o] : 0.f);
    }
}

// ---------------------------------------------------------------------------
// depthwise 3x3, SAME. Block: 256 threads = full 256-wide strip, 8 rows out.
// grid (32 row-strips, B*C)
// ---------------------------------------------------------------------------
__global__ __launch_bounds__(256)
void dwconv_kernel(const float* __restrict__ in, const float* __restrict__ w,
                   float* __restrict__ out, int C) {
    int z = blockIdx.y;
    int b = z / C, c = z - b * C;
    int h0 = blockIdx.x * 8;
    __shared__ float tile[10][258];
    const float* base = in + ((size_t)(b * C + c) << 16);
    int tid = threadIdx.x;
#pragma unroll
    for (int r = 0; r < 10; r++) {
        int gh = h0 - 1 + r;
        tile[r][tid + 1] = (gh >= 0 && gh < 256) ? base[gh * 256 + tid] : 0.f;
    }
    if (tid < 10) { tile[tid][0] = 0.f; tile[tid][257] = 0.f; }
    __syncthreads();
    const float* wc = w + c * 9;
    float w0 = wc[0], w1 = wc[1], w2 = wc[2], w3 = wc[3], w4 = wc[4],
          w5 = wc[5], w6 = wc[6], w7 = wc[7], w8 = wc[8];
    float* obase = out + ((size_t)(b * C + c) << 16) + h0 * 256 + tid;
#pragma unroll
    for (int y = 0; y < 8; y++) {
        float s = w0 * tile[y][tid]     + w1 * tile[y][tid + 1]     + w2 * tile[y][tid + 2]
                + w3 * tile[y + 1][tid] + w4 * tile[y + 1][tid + 1] + w5 * tile[y + 1][tid + 2]
                + w6 * tile[y + 2][tid] + w7 * tile[y + 2][tid + 1] + w8 * tile[y + 2][tid + 2];
        obase[y * 256] = s;
    }
}

// ---------------------------------------------------------------------------
// FFN gate: dw3x3 on channels c and c+128 of h (256ch), multiply.
// grid (32 row-strips, B*128)
// ---------------------------------------------------------------------------
__global__ __launch_bounds__(256)
void gate_kernel(const float* __restrict__ h, const float* __restrict__ wdw,
                 float* __restrict__ g) {
    int z = blockIdx.y;
    int b = z >> 7, c = z & 127;
    int h0 = blockIdx.x * 8;
    __shared__ float t1s[10][258];
    __shared__ float t2s[10][258];
    const float* base1 = h + ((size_t)(b * 256 + c) << 16);
    const float* base2 = h + ((size_t)(b * 256 + c + 128) << 16);
    int tid = threadIdx.x;
#pragma unroll
    for (int r = 0; r < 10; r++) {
        int gh = h0 - 1 + r;
        bool ok = (gh >= 0 && gh < 256);
        t1s[r][tid + 1] = ok ? base1[gh * 256 + tid] : 0.f;
        t2s[r][tid + 1] = ok ? base2[gh * 256 + tid] : 0.f;
    }
    if (tid < 10) {
        t1s[tid][0] = 0.f; t1s[tid][257] = 0.f;
        t2s[tid][0] = 0.f; t2s[tid][257] = 0.f;
    }
    __syncthreads();
    const float* wa = wdw + (size_t)c * 9;
    const float* wb = wdw + (size_t)(c + 128) * 9;
    float a0 = wa[0], a1 = wa[1], a2 = wa[2], a3 = wa[3], a4 = wa[4],
          a5 = wa[5], a6 = wa[6], a7 = wa[7], a8 = wa[8];
    float b0 = wb[0], b1 = wb[1], b2 = wb[2], b3 = wb[3], b4 = wb[4],
          b5 = wb[5], b6 = wb[6], b7 = wb[7], b8 = wb[8];
    float* obase = g + ((size_t)(b * 128 + c) << 16) + h0 * 256 + tid;
#pragma unroll
    for (int y = 0; y < 8; y++) {
        float s1 = a0 * t1s[y][tid]     + a1 * t1s[y][tid + 1]     + a2 * t1s[y][tid + 2]
                 + a3 * t1s[y + 1][tid] + a4 * t1s[y + 1][tid + 1] + a5 * t1s[y + 1][tid + 2]
                 + a6 * t1s[y + 2][tid] + a7 * t1s[y + 2][tid + 1] + a8 * t1s[y + 2][tid + 2];
        float s2 = b0 * t2s[y][tid]     + b1 * t2s[y][tid + 1]     + b2 * t2s[y][tid + 2]
                 + b3 * t2s[y + 1][tid] + b4 * t2s[y + 1][tid + 1] + b5 * t2s[y + 1][tid + 2]
                 + b6 * t2s[y + 2][tid] + b7 * t2s[y + 2][tid + 1] + b8 * t2s[y + 2][tid + 2];
        obase[y * 256] = s1 * s2;
    }
}

// ---------------------------------------------------------------------------
__global__ __launch_bounds__(256)
void attn_kernel(const float* __restrict__ qkv, float* __restrict__ attn) {
    int z = blockIdx.z;
    int b = z >> 5;
    int cg = (z & 31) * 8;
    int ph = blockIdx.y, pwg = blockIdx.x;
    __shared__ float sq[8][4][72];
    __shared__ float sk[8][4][72];

    int t = threadIdx.x;
    {
        int i = t >> 5, col = t & 31;
        int lp = col >> 3, j = col & 7;
        int off = (ph * 8 + i) * 256 + pwg * 32 + col;
#pragma unroll
        for (int cidx = 0; cidx < 8; cidx++) {
            int c = cg + cidx;
            sq[cidx][lp][i * 8 + j] = qkv[((size_t)(b * 768 + c)       << 16) + off];
            sk[cidx][lp][i * 8 + j] = qkv[((size_t)(b * 768 + 256 + c) << 16) + off];
        }
    }
    __syncthreads();

    int cp   = t >> 3;
    int cidx = cp >> 2;
    int lp   = cp & 3;
    int i    = t & 7;

    float acc[8];
#pragma unroll
    for (int j = 0; j < 8; j++) acc[j] = 0.f;

#pragma unroll
    for (int a = 0; a < 8; a++) {
        int ra = (i - a) & 7;
        float qr[8], kr[8];
        *reinterpret_cast<float4*>(&qr[0]) = *reinterpret_cast<const float4*>(&sq[cidx][lp][a * 8]);
        *reinterpret_cast<float4*>(&qr[4]) = *reinterpret_cast<const float4*>(&sq[cidx][lp][a * 8 + 4]);
        *reinterpret_cast<float4*>(&kr[0]) = *reinterpret_cast<const float4*>(&sk[cidx][lp][ra * 8]);
        *reinterpret_cast<float4*>(&kr[4]) = *reinterpret_cast<const float4*>(&sk[cidx][lp][ra * 8 + 4]);
#pragma unroll
        for (int bq = 0; bq < 8; bq++)
#pragma unroll
            for (int j = 0; j < 8; j++)
                acc[j] += qr[bq] * kr[(j - bq) & 7];
    }

    size_t obase = (((size_t)(b * 256 + cg + cidx)) << 16)
                 + (ph * 8 + i) * 256 + pwg * 32 + lp * 8;
    float4 o0, o1;
    o0.x = acc[0]; o0.y = acc[1]; o0.z = acc[2]; o0.w = acc[3];
    o1.x = acc[4]; o1.y = acc[5]; o1.z = acc[6]; o1.w = acc[7];
    *reinterpret_cast<float4*>(attn + obase)     = o0;
    *reinterpret_cast<float4*>(attn + obase + 4) = o1;
}

// ---------------------------------------------------------------------------
#define GEMM_SMEM 69632

extern "C" void kernel_launch(void* const* d_in, const int* in_sizes, int n_in,
                              void* d_out, int out_size) {
    const float* x      = (const float*)d_in[0];
    const float* n1w    = (const float*)d_in[1];
    const float* n1b    = (const float*)d_in[2];
    const float* w_h1   = (const float*)d_in[3];
    const float* w_dw1  = (const float*)d_in[4];
    const float* n2w    = (const float*)d_in[5];
    const float* n2b    = (const float*)d_in[6];
    const float* w_p1   = (const float*)d_in[7];
    const float* n3w    = (const float*)d_in[8];
    const float* n3b    = (const float*)d_in[9];
    const float* w_h2   = (const float*)d_in[10];
    const float* b_h2   = (const float*)d_in[11];
    const float* w_dw2  = (const float*)d_in[12];
    const float* w_p2   = (const float*)d_in[13];
    const float* scale1 = (const float*)d_in[14];
    const float* scale2 = (const float*)d_in[15];
    float* out = (float*)d_out;

    float *bufA, *bufB, *misc;
    cudaGetSymbolAddress((void**)&bufA, g_bufA);
    cudaGetSymbolAddress((void**)&bufB, g_bufB);
    cudaGetSymbolAddress((void**)&misc, g_misc);

    float* m1 = misc + OFF_M1;
    float* r1 = misc + OFF_R1;
    float* m2 = misc + OFF_M2;
    float* r2 = misc + OFF_R2;
    float* m3 = misc + OFF_M3;
    float* r3 = misc + OFF_R3;
    float* s1 = misc + OFF_S1;
    float* t1 = misc + OFF_T1;
    float* s2 = misc + OFF_S2;
    float* t2 = misc + OFF_T2;
    float* ds = misc + OFF_DS;
    float* dt = misc + OFF_DT;
    __nv_bfloat16* wbf = reinterpret_cast<__nv_bfloat16*>(misc + OFF_WBF);
    __nv_bfloat16* W1hi = wbf + WO_W1HI;
    __nv_bfloat16* W1lo = wbf + WO_W1LO;
    __nv_bfloat16* P1hi = wbf + WO_P1HI;
    __nv_bfloat16* P1lo = wbf + WO_P1LO;
    __nv_bfloat16* W2hi = wbf + WO_W2HI;
    __nv_bfloat16* W2lo = wbf + WO_W2LO;
    __nv_bfloat16* P2hi = wbf + WO_P2HI;
    __nv_bfloat16* P2lo = wbf + WO_P2LO;

    cudaFuncSetAttribute(mma_gemm<1>, cudaFuncAttributeMaxDynamicSharedMemorySize, GEMM_SMEM);
    cudaFuncSetAttribute(mma_gemm<2>, cudaFuncAttributeMaxDynamicSharedMemorySize, GEMM_SMEM);
    cudaFuncSetAttribute(mma_gemm<3>, cudaFuncAttributeMaxDynamicSharedMemorySize, GEMM_SMEM);

    // stats + weight folds / bf16 splits
    stats_kernel<<<512, 256>>>(x, m1, r1, 128);
    fold_kernel<<<96, 256>>>(w_h1, n1w, n1b, nullptr, W1hi, W1lo, s1, t1, 768, 128);
    fold_kernel<<<32, 256>>>(w_h2, n3w, n3b, b_h2,   W2hi, W2lo, s2, t2, 256, 128);
    fold_kernel<<<16, 256>>>(w_p1, nullptr, nullptr, nullptr, P1hi, P1lo, ds, dt, 128, 256);
    fold_kernel<<<16, 256>>>(w_p2, nullptr, nullptr, nullptr, P2hi, P2lo, ds, dt, 128, 128);

    // K1: hidden = LN1-folded conv1x1 (128 -> 768): stage x once, 6 m-blocks
    mma_gemm<1><<<dim3(1024, 1), 256, GEMM_SMEM>>>(W1hi, W1lo, x, bufA, 128, 128, 768, 6,
                                                   m1, r1, s1, t1,
                                                   nullptr, nullptr, nullptr, nullptr, nullptr);
    // K2: depthwise 3x3 over 768 channels
    dwconv_kernel<<<dim3(32, 1536), 256>>>(bufA, w_dw1, bufB, 768);

    // K3a: patch circular conv (q = ch 0..255, k = ch 256..511 of qkv)
    attn_kernel<<<dim3(8, 32, 64), 256>>>(bufB, bufA);
    stats_kernel<<<512, 256>>>(bufA, m2, r2, 256);

    // K3b: x1 = x + scale1 * ( w_p1 @ ( v * LN2(attn) ) )
    mma_gemm<3><<<dim3(1024, 1), 256, GEMM_SMEM>>>(P1hi, P1lo, bufA, bufA + OFF_X1, 256, 256, 128, 1,
                                                   m2, r2, nullptr, nullptr,
                                                   bufB, n2w, n2b, x, scale1);

    // FFN branch
    stats_kernel<<<512, 256>>>(bufA + OFF_X1, m3, r3, 128);
    mma_gemm<1><<<dim3(1024, 1), 256, GEMM_SMEM>>>(W2hi, W2lo, bufA + OFF_X1, bufB, 128, 128, 256, 2,
                                                   m3, r3, s2, t2,
                                                   nullptr, nullptr, nullptr, nullptr, nullptr);
    gate_kernel<<<dim3(32, 256), 256>>>(bufB, w_dw2, bufB + OFF_G);
    mma_gemm<2><<<dim3(1024, 1), 256, GEMM_SMEM>>>(P2hi, P2lo, bufB + OFF_G, out, 128, 128, 128, 1,
                                                   nullptr, nullptr, nullptr, nullptr,
                                                   nullptr, nullptr, nullptr,
                                                   bufA + OFF_X1, scale2);
}

// round 11
// speedup vs baseline: 3.0501x; 1.3356x over previous
#include <cuda_runtime.h>
#include <cuda_bf16.h>
#include <cstdint>

// ---------------------------------------------------------------------------
// FuseBlock: B=2, C=128, H=W=256.  (b,c,h,w), HW=65536, NPIX=131072.
// Single-term bf16 mma.sync GEMMs; all intermediates bf16; residuals fp32.
// ---------------------------------------------------------------------------

#define EPSV   1e-6f

__device__ float g_bufA[100663296];   // 2*768*65536 floats (views as bf16 too)
__device__ float g_bufB[100663296];
__device__ float g_misc[2097152];

#define OFF_M1   0
#define OFF_R1   131072
#define OFF_M2   262144
#define OFF_R2   393216
#define OFF_M3   524288
#define OFF_R3   655360
#define OFF_S1   786432
#define OFF_T1   787200
#define OFF_S2   787968
#define OFF_T2   788224
#define OFF_DS   788480
#define OFF_DT   788992
#define OFF_WBF  789504

// bf16-element offsets inside WBF region
#define WO_W1HI  0
#define WO_P1HI  98304
#define WO_W2HI  131072
#define WO_P2HI  163840

#define OFF_X1   50331648     // fp32 offset in bufA for x1
#define OFF_G16  50331648     // bf16 offset in bufB for g

// ---------------------------------------------------------------------------
__device__ __forceinline__ void mma16816(float* d, const uint32_t* a, const uint32_t* b) {
    asm volatile(
        "mma.sync.aligned.m16n8k16.row.col.f32.bf16.bf16.f32 "
        "{%0,%1,%2,%3}, {%4,%5,%6,%7}, {%8,%9}, {%0,%1,%2,%3};"
        : "+f"(d[0]), "+f"(d[1]), "+f"(d[2]), "+f"(d[3])
        : "r"(a[0]), "r"(a[1]), "r"(a[2]), "r"(a[3]), "r"(b[0]), "r"(b[1]));
}

__device__ __forceinline__ uint32_t pack_f2(float a, float b) {
    __nv_bfloat16 ha = __float2bfloat16(a);
    __nv_bfloat16 hb = __float2bfloat16(b);
    return (uint32_t)__bfloat16_as_ushort(ha) | ((uint32_t)__bfloat16_as_ushort(hb) << 16);
}
__device__ __forceinline__ float2 bf2_f2(uint32_t u) {
    float2 r;
    r.x = __uint_as_float(u << 16);
    r.y = __uint_as_float(u & 0xFFFF0000u);
    return r;
}

// ---------------------------------------------------------------------------
// mma GEMM: C[mblocks*128 out-ch, 128 pix @ n0] = A[m,K] @ B[K, pix]
// MODE 1: B fp32 planar; out bf16 = colRstd*(acc - colMean*rowS) + rowT
// MODE 2: B bf16 planar; out fp32 = Xres + acc*scaleRow
// MODE 3: B = v*LN2(attn) (both bf16); out fp32 = Xres + acc*scaleRow;
//         fused per-pixel stats (mean/rstd over the 128 output channels).
// smem: BsHi word[64 kpair][136 pix]  (34816 B)
// ---------------------------------------------------------------------------
#define BROW 136
#define GEMM_SMEM 36864

template <int MODE>
__global__ __launch_bounds__(256)
void mma_gemm(const __nv_bfloat16* __restrict__ Ahi, const void* __restrict__ Bv,
              void* __restrict__ Cv, int K, int CB, int CO, int mblocks,
              const float* __restrict__ colMean, const float* __restrict__ colRstd,
              const float* __restrict__ rowS, const float* __restrict__ rowT,
              const __nv_bfloat16* __restrict__ vbuf, const float* __restrict__ lnW,
              const float* __restrict__ lnB, const float* __restrict__ Xres,
              const float* __restrict__ scaleRow,
              float* __restrict__ m3out, float* __restrict__ r3out)
{
    extern __shared__ __align__(16) char smem[];
    uint32_t* BsHi = reinterpret_cast<uint32_t*>(smem);

    const int tid = threadIdx.x;
    const int wid = tid >> 5;
    const int lane = tid & 31;
    const int n0 = blockIdx.x * 128;
    const int bg = n0 >> 16;
    const int hw0 = n0 & 65535;
    const int warp_m = wid & 3;
    const int warp_n = wid >> 2;
    const int g  = lane >> 2;
    const int th = lane & 3;

    const int nchunks = K >> 7;

    for (int mb = 0; mb < mblocks; mb++) {
        const int m0 = mb * 128;

        float acc[2][8][4];
#pragma unroll
        for (int mt = 0; mt < 2; mt++)
#pragma unroll
            for (int nt = 0; nt < 8; nt++)
#pragma unroll
                for (int r = 0; r < 4; r++) acc[mt][nt][r] = 0.f;

        for (int ch = 0; ch < nchunks; ch++) {
            const int kc = ch << 7;

            if (mb == 0) {
                if (ch) __syncthreads();
                // ---- stage B chunk: word[kp][pix] = (bf16 k0, bf16 k1) ----
#pragma unroll
                for (int it = 0; it < 8; it++) {
                    int idx = tid + it * 256;
                    int kp = idx >> 5;
                    int pg = (idx & 31) * 4;
                    int k0 = kc + kp * 2;
                    uint4 W;
                    if (MODE == 1) {
                        const float* Bf = (const float*)Bv;
                        float4 va = *reinterpret_cast<const float4*>(
                            Bf + (((size_t)(bg * CB + k0))     << 16) + hw0 + pg);
                        float4 vb = *reinterpret_cast<const float4*>(
                            Bf + (((size_t)(bg * CB + k0 + 1)) << 16) + hw0 + pg);
                        W.x = pack_f2(va.x, vb.x);
                        W.y = pack_f2(va.y, vb.y);
                        W.z = pack_f2(va.z, vb.z);
                        W.w = pack_f2(va.w, vb.w);
                    } else if (MODE == 2) {
                        const __nv_bfloat16* Bb = (const __nv_bfloat16*)Bv;
                        uint2 u = *reinterpret_cast<const uint2*>(
                            Bb + (((size_t)(bg * CB + k0))     << 16) + hw0 + pg);
                        uint2 v = *reinterpret_cast<const uint2*>(
                            Bb + (((size_t)(bg * CB + k0 + 1)) << 16) + hw0 + pg);
                        W.x = __byte_perm(u.x, v.x, 0x5410);
                        W.y = __byte_perm(u.x, v.x, 0x7632);
                        W.z = __byte_perm(u.y, v.y, 0x5410);
                        W.w = __byte_perm(u.y, v.y, 0x7632);
                    } else { // MODE 3
                        const __nv_bfloat16* Ab = (const __nv_bfloat16*)Bv;
                        uint2 ua0 = *reinterpret_cast<const uint2*>(
                            Ab + (((size_t)(bg * 256 + k0))     << 16) + hw0 + pg);
                        uint2 ua1 = *reinterpret_cast<const uint2*>(
                            Ab + (((size_t)(bg * 256 + k0 + 1)) << 16) + hw0 + pg);
                        uint2 uv0 = *reinterpret_cast<const uint2*>(
                            vbuf + (((size_t)(bg * 768 + 512 + k0))     << 16) + hw0 + pg);
                        uint2 uv1 = *reinterpret_cast<const uint2*>(
                            vbuf + (((size_t)(bg * 768 + 512 + k0 + 1)) << 16) + hw0 + pg);
                        float4 m4 = *reinterpret_cast<const float4*>(colMean + n0 + pg);
                        float4 r4 = *reinterpret_cast<const float4*>(colRstd + n0 + pg);
                        float wc0 = lnW[k0], bc0 = lnB[k0];
                        float wc1 = lnW[k0 + 1], bc1 = lnB[k0 + 1];
                        float2 a0 = bf2_f2(ua0.x), a1 = bf2_f2(ua0.y);
                        float2 c0 = bf2_f2(ua1.x), c1 = bf2_f2(ua1.y);
                        float2 v0 = bf2_f2(uv0.x), v1 = bf2_f2(uv0.y);
                        float2 w0 = bf2_f2(uv1.x), w1 = bf2_f2(uv1.y);
                        float r0a = v0.x * ((a0.x - m4.x) * r4.x * wc0 + bc0);
                        float r0b = v0.y * ((a0.y - m4.y) * r4.y * wc0 + bc0);
                        float r0c = v1.x * ((a1.x - m4.z) * r4.z * wc0 + bc0);
                        float r0d = v1.y * ((a1.y - m4.w) * r4.w * wc0 + bc0);
                        float r1a = w0.x * ((c0.x - m4.x) * r4.x * wc1 + bc1);
                        float r1b = w0.y * ((c0.y - m4.y) * r4.y * wc1 + bc1);
                        float r1c = w1.x * ((c1.x - m4.z) * r4.z * wc1 + bc1);
                        float r1d = w1.y * ((c1.y - m4.w) * r4.w * wc1 + bc1);
                        W.x = pack_f2(r0a, r1a);
                        W.y = pack_f2(r0b, r1b);
                        W.z = pack_f2(r0c, r1c);
                        W.w = pack_f2(r0d, r1d);
                    }
                    *reinterpret_cast<uint4*>(BsHi + kp * BROW + pg) = W;
                }
                __syncthreads();
            }

            // ---- 8 k-steps of 16 ----
#pragma unroll
            for (int ks = 0; ks < 8; ks++) {
                uint32_t ah[2][4];
#pragma unroll
                for (int mt = 0; mt < 2; mt++) {
                    int r = m0 + warp_m * 32 + mt * 16 + g;
                    size_t base = (size_t)r * K + kc + ks * 16 + th * 2;
                    ah[mt][0] = *reinterpret_cast<const uint32_t*>(Ahi + base);
                    ah[mt][1] = *reinterpret_cast<const uint32_t*>(Ahi + base + (size_t)8 * K);
                    ah[mt][2] = *reinterpret_cast<const uint32_t*>(Ahi + base + 8);
                    ah[mt][3] = *reinterpret_cast<const uint32_t*>(Ahi + base + (size_t)8 * K + 8);
                }
                const int kp0 = ks * 8 + th;
                const int kp1 = ks * 8 + 4 + th;
#pragma unroll
                for (int nt = 0; nt < 8; nt++) {
                    int n = warp_n * 64 + nt * 8 + g;
                    uint32_t bh[2];
                    bh[0] = BsHi[kp0 * BROW + n];
                    bh[1] = BsHi[kp1 * BROW + n];
#pragma unroll
                    for (int mt = 0; mt < 2; mt++)
                        mma16816(acc[mt][nt], ah[mt], bh);
                }
            }
        }

        // ---- epilogue ----
        float sAcc[16], qAcc[16];
        if (MODE == 3) {
#pragma unroll
            for (int i = 0; i < 16; i++) { sAcc[i] = 0.f; qAcc[i] = 0.f; }
        }
#pragma unroll
        for (int mt = 0; mt < 2; mt++) {
#pragma unroll
            for (int half = 0; half < 2; half++) {
                int o = m0 + warp_m * 32 + mt * 16 + g + half * 8;
                if (MODE == 1) {
                    float sv = rowS[o], tv = rowT[o];
                    __nv_bfloat16* Cb = (__nv_bfloat16*)Cv;
#pragma unroll
                    for (int nt = 0; nt < 8; nt++) {
                        int col = warp_n * 64 + nt * 8 + th * 2;
                        float2 cm = *reinterpret_cast<const float2*>(colMean + n0 + col);
                        float2 cr = *reinterpret_cast<const float2*>(colRstd + n0 + col);
                        float d0 = cr.x * (acc[mt][nt][half * 2 + 0] - cm.x * sv) + tv;
                        float d1 = cr.y * (acc[mt][nt][half * 2 + 1] - cm.y * sv) + tv;
                        *reinterpret_cast<uint32_t*>(
                            Cb + (((size_t)(bg * CO + o)) << 16) + hw0 + col) = pack_f2(d0, d1);
                    }
                } else {
                    float sc = scaleRow[o];
                    float* Cf = (float*)Cv;
#pragma unroll
                    for (int nt = 0; nt < 8; nt++) {
                        int col = warp_n * 64 + nt * 8 + th * 2;
                        size_t ix = (((size_t)(bg * CO + o)) << 16) + hw0 + col;
                        float2 xr = *reinterpret_cast<const float2*>(Xres + ix);
                        float2 ov;
                        ov.x = xr.x + acc[mt][nt][half * 2 + 0] * sc;
                        ov.y = xr.y + acc[mt][nt][half * 2 + 1] * sc;
                        *reinterpret_cast<float2*>(Cf + ix) = ov;
                        if (MODE == 3) {
                            sAcc[nt * 2 + 0] += ov.x;
                            qAcc[nt * 2 + 0] += ov.x * ov.x;
                            sAcc[nt * 2 + 1] += ov.y;
                            qAcc[nt * 2 + 1] += ov.y * ov.y;
                        }
                    }
                }
            }
        }

        // ---- fused per-pixel stats over the 128 channels (MODE 3) ----
        if (MODE == 3) {
            // reduce over g (lanes differing in bits 2..4)
#pragma unroll
            for (int i = 0; i < 16; i++) {
#pragma unroll
                for (int off = 4; off <= 16; off <<= 1) {
                    sAcc[i] += __shfl_xor_sync(0xFFFFFFFFu, sAcc[i], off);
                    qAcc[i] += __shfl_xor_sync(0xFFFFFFFFu, qAcc[i], off);
                }
            }
            __syncthreads();               // smem (BsHi) no longer needed
            float* sPart = reinterpret_cast<float*>(smem);          // [4][128]
            float* qPart = sPart + 512;                             // [4][128]
            if (lane < 4) {
#pragma unroll
                for (int nt = 0; nt < 8; nt++) {
#pragma unroll
                    for (int c = 0; c < 2; c++) {
                        int col = warp_n * 64 + nt * 8 + lane * 2 + c;
                        sPart[warp_m * 128 + col] = sAcc[nt * 2 + c];
                        qPart[warp_m * 128 + col] = qAcc[nt * 2 + c];
                    }
                }
            }
            __syncthreads();
            if (tid < 128) {
                float s = sPart[tid] + sPart[128 + tid] + sPart[256 + tid] + sPart[384 + tid];
                float q = qPart[tid] + qPart[128 + tid] + qPart[256 + tid] + qPart[384 + tid];
                float m = s * (1.f / 128.f);
                float var = q * (1.f / 128.f) - m * m;
                m3out[n0 + tid] = m;
                r3out[n0 + tid] = rsqrtf(var + EPSV);
            }
        }
    }
}

// ---------------------------------------------------------------------------
// per-pixel channel mean / rstd  (fp32 input)
// ---------------------------------------------------------------------------
__global__ void stats_kernel(const float* __restrict__ in, float* __restrict__ mean,
                             float* __restrict__ rstd, int C) {
    int p = blockIdx.x * blockDim.x + threadIdx.x;
    int b = p >> 16, hw = p & 65535;
    const float* base = in + ((size_t)(b * C) << 16) + hw;
    float s = 0.f, ss = 0.f;
    for (int c = 0; c < C; c += 4) {
        float v0 = base[(size_t)(c + 0) << 16];
        float v1 = base[(size_t)(c + 1) << 16];
        float v2 = base[(size_t)(c + 2) << 16];
        float v3 = base[(size_t)(c + 3) << 16];
        s  += v0 + v1 + v2 + v3;
        ss += v0 * v0 + v1 * v1 + v2 * v2 + v3 * v3;
    }
    float invC = 1.f / (float)C;
    float m = s * invC;
    float var = ss * invC - m * m;
    mean[p] = m;
    rstd[p] = rsqrtf(var + EPSV);
}

// bf16-input variant (for attn stats)
__global__ void stats_bf16_kernel(const __nv_bfloat16* __restrict__ in,
                                  float* __restrict__ mean, float* __restrict__ rstd, int C) {
    int p = blockIdx.x * blockDim.x + threadIdx.x;
    int b = p >> 16, hw = p & 65535;
    const __nv_bfloat16* base = in + ((size_t)(b * C) << 16) + hw;
    float s = 0.f, ss = 0.f;
    for (int c = 0; c < C; c += 4) {
        float v0 = __bfloat162float(base[(size_t)(c + 0) << 16]);
        float v1 = __bfloat162float(base[(size_t)(c + 1) << 16]);
        float v2 = __bfloat162float(base[(size_t)(c + 2) << 16]);
        float v3 = __bfloat162float(base[(size_t)(c + 3) << 16]);
        s  += v0 + v1 + v2 + v3;
        ss += v0 * v0 + v1 * v1 + v2 * v2 + v3 * v3;
    }
    float invC = 1.f / (float)C;
    float m = s * invC;
    float var = ss * invC - m * m;
    mean[p] = m;
    rstd[p] = rsqrtf(var + EPSV);
}

// ---------------------------------------------------------------------------
// fold LN into conv weight + bf16 (hi-only). One WARP per output row.
// ---------------------------------------------------------------------------
__global__ void fold_kernel(const float* __restrict__ wmat, const float* __restrict__ nw,
                            const float* __restrict__ nb, const float* __restrict__ bias,
                            __nv_bfloat16* __restrict__ whi,
                            float* __restrict__ srow, float* __restrict__ trow,
                            int M, int K) {
    int o = blockIdx.x * (blockDim.x >> 5) + (threadIdx.x >> 5);
    int lane = threadIdx.x & 31;
    if (o >= M) return;
    float s = 0.f, t = 0.f;
    for (int c = lane; c < K; c += 32) {
        float wv  = wmat[o * K + c];
        float wpv = nw ? wv * nw[c] : wv;
        whi[o * K + c] = __float2bfloat16(wpv);
        s += wpv;
        if (nb) t += wv * nb[c];
    }
#pragma unroll
    for (int off = 16; off; off >>= 1) {
        s += __shfl_xor_sync(0xFFFFFFFFu, s, off);
        t += __shfl_xor_sync(0xFFFFFFFFu, t, off);
    }
    if (lane == 0) {
        srow[o] = s;
        trow[o] = t + (bias ? bias[o] : 0.f);
    }
}

// ---------------------------------------------------------------------------
// depthwise 3x3 on bf16, SAME. 256-wide strip, 8 rows. grid (32, B*C)
// ---------------------------------------------------------------------------
__global__ __launch_bounds__(256)
void dwconv_kernel(const __nv_bfloat16* __restrict__ in, const float* __restrict__ w,
                   __nv_bfloat16* __restrict__ out, int C) {
    int z = blockIdx.y;
    int b = z / C, c = z - b * C;
    int h0 = blockIdx.x * 8;
    __shared__ float tile[10][258];
    const __nv_bfloat16* base = in + ((size_t)(b * C + c) << 16);
    int tid = threadIdx.x;
#pragma unroll
    for (int r = 0; r < 10; r++) {
        int gh = h0 - 1 + r;
        tile[r][tid + 1] = (gh >= 0 && gh < 256) ? __bfloat162float(base[gh * 256 + tid]) : 0.f;
    }
    if (tid < 10) { tile[tid][0] = 0.f; tile[tid][257] = 0.f; }
    __syncthreads();
    const float* wc = w + c * 9;
    float w0 = wc[0], w1 = wc[1], w2 = wc[2], w3 = wc[3], w4 = wc[4],
          w5 = wc[5], w6 = wc[6], w7 = wc[7], w8 = wc[8];
    __nv_bfloat16* obase = out + ((size_t)(b * C + c) << 16) + h0 * 256 + tid;
#pragma unroll
    for (int y = 0; y < 8; y++) {
        float s = w0 * tile[y][tid]     + w1 * tile[y][tid + 1]     + w2 * tile[y][tid + 2]
                + w3 * tile[y + 1][tid] + w4 * tile[y + 1][tid + 1] + w5 * tile[y + 1][tid + 2]
                + w6 * tile[y + 2][tid] + w7 * tile[y + 2][tid + 1] + w8 * tile[y + 2][tid + 2];
        obase[y * 256] = __float2bfloat16(s);
    }
}

// ---------------------------------------------------------------------------
// FFN gate on bf16: dw3x3 on channels c and c+128 of h, multiply. grid (32, B*128)
// ---------------------------------------------------------------------------
__global__ __launch_bounds__(256)
void gate_kernel(const __nv_bfloat16* __restrict__ h, const float* __restrict__ wdw,
                 __nv_bfloat16* __restrict__ g) {
    int z = blockIdx.y;
    int b = z >> 7, c = z & 127;
    int h0 = blockIdx.x * 8;
    __shared__ float t1s[10][258];
    __shared__ float t2s[10][258];
    const __nv_bfloat16* base1 = h + ((size_t)(b * 256 + c) << 16);
    const __nv_bfloat16* base2 = h + ((size_t)(b * 256 + c + 128) << 16);
    int tid = threadIdx.x;
#pragma unroll
    for (int r = 0; r < 10; r++) {
        int gh = h0 - 1 + r;
        bool ok = (gh >= 0 && gh < 256);
        t1s[r][tid + 1] = ok ? __bfloat162float(base1[gh * 256 + tid]) : 0.f;
        t2s[r][tid + 1] = ok ? __bfloat162float(base2[gh * 256 + tid]) : 0.f;
    }
    if (tid < 10) {
        t1s[tid][0] = 0.f; t1s[tid][257] = 0.f;
        t2s[tid][0] = 0.f; t2s[tid][257] = 0.f;
    }
    __syncthreads();
    const float* wa = wdw + (size_t)c * 9;
    const float* wb = wdw + (size_t)(c + 128) * 9;
    float a0 = wa[0], a1 = wa[1], a2 = wa[2], a3 = wa[3], a4 = wa[4],
          a5 = wa[5], a6 = wa[6], a7 = wa[7], a8 = wa[8];
    float b0 = wb[0], b1 = wb[1], b2 = wb[2], b3 = wb[3], b4 = wb[4],
          b5 = wb[5], b6 = wb[6], b7 = wb[7], b8 = wb[8];
    __nv_bfloat16* obase = g + ((size_t)(b * 128 + c) << 16) + h0 * 256 + tid;
#pragma unroll
    for (int y = 0; y < 8; y++) {
        float s1 = a0 * t1s[y][tid]     + a1 * t1s[y][tid + 1]     + a2 * t1s[y][tid + 2]
                 + a3 * t1s[y + 1][tid] + a4 * t1s[y + 1][tid + 1] + a5 * t1s[y + 1][tid + 2]
                 + a6 * t1s[y + 2][tid] + a7 * t1s[y + 2][tid + 1] + a8 * t1s[y + 2][tid + 2];
        float s2 = b0 * t2s[y][tid]     + b1 * t2s[y][tid + 1]     + b2 * t2s[y][tid + 2]
                 + b3 * t2s[y + 1][tid] + b4 * t2s[y + 1][tid + 1] + b5 * t2s[y + 1][tid + 2]
                 + b6 * t2s[y + 2][tid] + b7 * t2s[y + 2][tid + 1] + b8 * t2s[y + 2][tid + 2];
        obase[y * 256] = __float2bfloat16(s1 * s2);
    }
}

// ---------------------------------------------------------------------------
// patch circular conv on bf16 qkv -> bf16 attn
// ---------------------------------------------------------------------------
__global__ __launch_bounds__(256)
void attn_kernel(const __nv_bfloat16* __restrict__ qkv, __nv_bfloat16* __restrict__ attn) {
    int z = blockIdx.z;
    int b = z >> 5;
    int cg = (z & 31) * 8;
    int ph = blockIdx.y, pwg = blockIdx.x;
    __shared__ float sq[8][4][72];
    __shared__ float sk[8][4][72];

    int t = threadIdx.x;
    {
        int i = t >> 5, col = t & 31;
        int lp = col >> 3, j = col & 7;
        int off = (ph * 8 + i) * 256 + pwg * 32 + col;
#pragma unroll
        for (int cidx = 0; cidx < 8; cidx++) {
            int c = cg + cidx;
            sq[cidx][lp][i * 8 + j] = __bfloat162float(qkv[((size_t)(b * 768 + c)       << 16) + off]);
            sk[cidx][lp][i * 8 + j] = __bfloat162float(qkv[((size_t)(b * 768 + 256 + c) << 16) + off]);
        }
    }
    __syncthreads();

    int cp   = t >> 3;
    int cidx = cp >> 2;
    int lp   = cp & 3;
    int i    = t & 7;

    float acc[8];
#pragma unroll
    for (int j = 0; j < 8; j++) acc[j] = 0.f;

#pragma unroll
    for (int a = 0; a < 8; a++) {
        int ra = (i - a) & 7;
        float qr[8], kr[8];
        *reinterpret_cast<float4*>(&qr[0]) = *reinterpret_cast<const float4*>(&sq[cidx][lp][a * 8]);
        *reinterpret_cast<float4*>(&qr[4]) = *reinterpret_cast<const float4*>(&sq[cidx][lp][a * 8 + 4]);
        *reinterpret_cast<float4*>(&kr[0]) = *reinterpret_cast<const float4*>(&sk[cidx][lp][ra * 8]);
        *reinterpret_cast<float4*>(&kr[4]) = *reinterpret_cast<const float4*>(&sk[cidx][lp][ra * 8 + 4]);
#pragma unroll
        for (int bq = 0; bq < 8; bq++)
#pragma unroll
            for (int j = 0; j < 8; j++)
                acc[j] += qr[bq] * kr[(j - bq) & 7];
    }

    size_t obase = (((size_t)(b * 256 + cg + cidx)) << 16)
                 + (ph * 8 + i) * 256 + pwg * 32 + lp * 8;
    uint4 ov;
    ov.x = pack_f2(acc[0], acc[1]);
    ov.y = pack_f2(acc[2], acc[3]);
    ov.z = pack_f2(acc[4], acc[5]);
    ov.w = pack_f2(acc[6], acc[7]);
    *reinterpret_cast<uint4*>(attn + obase) = ov;
}

// ---------------------------------------------------------------------------
extern "C" void kernel_launch(void* const* d_in, const int* in_sizes, int n_in,
                              void* d_out, int out_size) {
    const float* x      = (const float*)d_in[0];
    const float* n1w    = (const float*)d_in[1];
    const float* n1b    = (const float*)d_in[2];
    const float* w_h1   = (const float*)d_in[3];
    const float* w_dw1  = (const float*)d_in[4];
    const float* n2w    = (const float*)d_in[5];
    const float* n2b    = (const float*)d_in[6];
    const float* w_p1   = (const float*)d_in[7];
    const float* n3w    = (const float*)d_in[8];
    const float* n3b    = (const float*)d_in[9];
    const float* w_h2   = (const float*)d_in[10];
    const float* b_h2   = (const float*)d_in[11];
    const float* w_dw2  = (const float*)d_in[12];
    const float* w_p2   = (const float*)d_in[13];
    const float* scale1 = (const float*)d_in[14];
    const float* scale2 = (const float*)d_in[15];
    float* out = (float*)d_out;

    float *bufA, *bufB, *misc;
    cudaGetSymbolAddress((void**)&bufA, g_bufA);
    cudaGetSymbolAddress((void**)&bufB, g_bufB);
    cudaGetSymbolAddress((void**)&misc, g_misc);

    __nv_bfloat16* bA16 = reinterpret_cast<__nv_bfloat16*>(bufA);
    __nv_bfloat16* bB16 = reinterpret_cast<__nv_bfloat16*>(bufB);

    float* m1 = misc + OFF_M1;
    float* r1 = misc + OFF_R1;
    float* m2 = misc + OFF_M2;
    float* r2 = misc + OFF_R2;
    float* m3 = misc + OFF_M3;
    float* r3 = misc + OFF_R3;
    float* s1 = misc + OFF_S1;
    float* t1 = misc + OFF_T1;
    float* s2 = misc + OFF_S2;
    float* t2 = misc + OFF_T2;
    float* ds = misc + OFF_DS;
    float* dt = misc + OFF_DT;
    __nv_bfloat16* wbf = reinterpret_cast<__nv_bfloat16*>(misc + OFF_WBF);
    __nv_bfloat16* W1hi = wbf + WO_W1HI;
    __nv_bfloat16* P1hi = wbf + WO_P1HI;
    __nv_bfloat16* W2hi = wbf + WO_W2HI;
    __nv_bfloat16* P2hi = wbf + WO_P2HI;

    cudaFuncSetAttribute(mma_gemm<1>, cudaFuncAttributeMaxDynamicSharedMemorySize, GEMM_SMEM);
    cudaFuncSetAttribute(mma_gemm<2>, cudaFuncAttributeMaxDynamicSharedMemorySize, GEMM_SMEM);
    cudaFuncSetAttribute(mma_gemm<3>, cudaFuncAttributeMaxDynamicSharedMemorySize, GEMM_SMEM);

    // stats + weight folds
    stats_kernel<<<512, 256>>>(x, m1, r1, 128);
    fold_kernel<<<96, 256>>>(w_h1, n1w, n1b, nullptr, W1hi, s1, t1, 768, 128);
    fold_kernel<<<32, 256>>>(w_h2, n3w, n3b, b_h2,   W2hi, s2, t2, 256, 128);
    fold_kernel<<<16, 256>>>(w_p1, nullptr, nullptr, nullptr, P1hi, ds, dt, 128, 256);
    fold_kernel<<<16, 256>>>(w_p2, nullptr, nullptr, nullptr, P2hi, ds, dt, 128, 128);

    // K1: hidden(bf16, 768ch in bufA) = LN1-folded conv1x1(x)
    mma_gemm<1><<<dim3(1024, 1), 256, GEMM_SMEM>>>(W1hi, x, bA16, 128, 128, 768, 6,
                                                   m1, r1, s1, t1,
                                                   nullptr, nullptr, nullptr, nullptr, nullptr,
                                                   nullptr, nullptr);
    // K2: depthwise 3x3 (bf16 -> bf16), qkv in bufB
    dwconv_kernel<<<dim3(32, 1536), 256>>>(bA16, w_dw1, bB16, 768);

    // K3a: patch circular conv -> attn (bf16, bufA)
    attn_kernel<<<dim3(8, 32, 64), 256>>>(bB16, bA16);
    stats_bf16_kernel<<<512, 256>>>(bA16, m2, r2, 256);

    // K3b: x1(fp32) = x + scale1 * ( w_p1 @ (v * LN2(attn)) );  fused stats -> m3,r3
    mma_gemm<3><<<dim3(1024, 1), 256, GEMM_SMEM>>>(P1hi, bA16, bufA + OFF_X1, 256, 256, 128, 1,
                                                   m2, r2, nullptr, nullptr,
                                                   bB16, n2w, n2b, x, scale1,
                                                   m3, r3);

    // K4: h(bf16, 256ch in bufB) = LN3-folded conv1x1(x1) + b_h2
    mma_gemm<1><<<dim3(1024, 1), 256, GEMM_SMEM>>>(W2hi, bufA + OFF_X1, bB16, 128, 128, 256, 2,
                                                   m3, r3, s2, t2,
                                                   nullptr, nullptr, nullptr, nullptr, nullptr,
                                                   nullptr, nullptr);
    // K5a: gate (bf16 -> bf16)
    gate_kernel<<<dim3(32, 256), 256>>>(bB16, w_dw2, bB16 + OFF_G16);
    // K5b: out(fp32) = x1 + scale2 * (w_p2 @ g)
    mma_gemm<2><<<dim3(1024, 1), 256, GEMM_SMEM>>>(P2hi, bB16 + OFF_G16, out, 128, 128, 128, 1,
                                                   nullptr, nullptr, nullptr, nullptr,
                                                   nullptr, nullptr, nullptr,
                                                   bufA + OFF_X1, scale2,
                                                   nullptr, nullptr);
}